// round 9
// baseline (speedup 1.0000x reference)
#include <cuda_runtime.h>
#include <cuda_bf16.h>
#include <math_constants.h>

#define BATCH   2
#define SEQ     2048
#define NHEADS  16
#define DHEAD   128
#define DMODEL  2048
#define DM3     6144
#define MTOT    4096

// Scratch (device globals)
__device__ __nv_bfloat16 g_qkvh[(size_t)MTOT * DM3];
__device__ __nv_bfloat16 g_qkvl[(size_t)MTOT * DM3];
__device__ __nv_bfloat16 g_xh[(size_t)MTOT * DMODEL];
__device__ __nv_bfloat16 g_xl[(size_t)MTOT * DMODEL];
__device__ __nv_bfloat16 g_wqkvth[(size_t)DM3 * DMODEL];   // [N=6144][K=2048]
__device__ __nv_bfloat16 g_wqkvtl[(size_t)DM3 * DMODEL];
__device__ __nv_bfloat16 g_woutth[(size_t)DMODEL * DMODEL];
__device__ __nv_bfloat16 g_wouttl[(size_t)DMODEL * DMODEL];
__device__ __nv_bfloat16 g_attnh[(size_t)MTOT * DMODEL];
__device__ __nv_bfloat16 g_attnl[(size_t)MTOT * DMODEL];

// ---------------------------------------------------------------------------
// Helpers
// ---------------------------------------------------------------------------
static __device__ __forceinline__ void mma_bf16(
    float& c0, float& c1, float& c2, float& c3,
    unsigned a0, unsigned a1, unsigned a2, unsigned a3,
    unsigned b0, unsigned b1)
{
    asm volatile(
        "mma.sync.aligned.m16n8k16.row.col.f32.bf16.bf16.f32 "
        "{%0,%1,%2,%3}, {%4,%5,%6,%7}, {%8,%9}, {%0,%1,%2,%3};\n"
        : "+f"(c0), "+f"(c1), "+f"(c2), "+f"(c3)
        : "r"(a0), "r"(a1), "r"(a2), "r"(a3), "r"(b0), "r"(b1));
}
static __device__ __forceinline__ void ldsm_x4(
    unsigned& r0, unsigned& r1, unsigned& r2, unsigned& r3, unsigned addr)
{
    asm volatile("ldmatrix.sync.aligned.m8n8.x4.shared.b16 {%0,%1,%2,%3}, [%4];\n"
                 : "=r"(r0), "=r"(r1), "=r"(r2), "=r"(r3) : "r"(addr));
}
static __device__ __forceinline__ void ldsm_x4t(
    unsigned& r0, unsigned& r1, unsigned& r2, unsigned& r3, unsigned addr)
{
    asm volatile("ldmatrix.sync.aligned.m8n8.x4.trans.shared.b16 {%0,%1,%2,%3}, [%4];\n"
                 : "=r"(r0), "=r"(r1), "=r"(r2), "=r"(r3) : "r"(addr));
}
static __device__ __forceinline__ unsigned bf2u(__nv_bfloat162 v) {
    return *reinterpret_cast<unsigned*>(&v);
}
static __device__ __forceinline__ void split4(float4 f, uint2& hi, uint2& lo) {
    __nv_bfloat162 h0 = __floats2bfloat162_rn(f.x, f.y);
    __nv_bfloat162 h1 = __floats2bfloat162_rn(f.z, f.w);
    float hx = __low2float(h0), hy = __high2float(h0);
    float hz = __low2float(h1), hw = __high2float(h1);
    __nv_bfloat162 l0 = __floats2bfloat162_rn(f.x - hx, f.y - hy);
    __nv_bfloat162 l1 = __floats2bfloat162_rn(f.z - hz, f.w - hw);
    hi.x = bf2u(h0); hi.y = bf2u(h1);
    lo.x = bf2u(l0); lo.y = bf2u(l1);
}
static __device__ __forceinline__ void cpa16(unsigned saddr, const void* g) {
    asm volatile("cp.async.cg.shared.global [%0], [%1], 16;\n"
                 :: "r"(saddr), "l"(g));
}

// ---------------------------------------------------------------------------
// Prep kernels: fp32 -> bf16 hi/lo planes
// ---------------------------------------------------------------------------
__global__ __launch_bounds__(256) void split_rm_kernel(
    const float4* __restrict__ src, uint2* __restrict__ h, uint2* __restrict__ l,
    int n4)
{
    int i = blockIdx.x * 256 + threadIdx.x;
    if (i < n4) {
        uint2 hi, lo;
        split4(src[i], hi, lo);
        h[i] = hi; l[i] = lo;
    }
}

// W [K][N] fp32 -> Wt hi/lo [N][K] bf16
__global__ __launch_bounds__(256) void split_tr_kernel(
    const float* __restrict__ W,
    __nv_bfloat16* __restrict__ th, __nv_bfloat16* __restrict__ tl,
    int K, int N)
{
    __shared__ float tile[32][33];
    const int n0 = blockIdx.x * 32, k0 = blockIdx.y * 32;
    const int tx = threadIdx.x & 31, ty = threadIdx.x >> 5;  // 32 x 8
    #pragma unroll
    for (int i = 0; i < 32; i += 8)
        tile[ty + i][tx] = W[(size_t)(k0 + ty + i) * N + (n0 + tx)];
    __syncthreads();
    #pragma unroll
    for (int i = 0; i < 32; i += 8) {
        float v = tile[tx][ty + i];
        __nv_bfloat16 hb = __float2bfloat16(v);
        __nv_bfloat16 lb = __float2bfloat16(v - __bfloat162float(hb));
        size_t o = (size_t)(n0 + ty + i) * K + (k0 + tx);
        th[o] = hb; tl[o] = lb;
    }
}

// ---------------------------------------------------------------------------
// Plane GEMM: C = (Ah+Al)[M,K] @ (Bh+Bl)^T[N,K] + bias
// Block 128x128, ktile 32, 256 threads = 8 warps (4m x 2n), warp tile 32x64.
// Smem: per tile row 128B = 8 chunks of 16B: [4 hi | 4 lo], position
// swizzled chunk^(row&7) -> conflict-free ldmatrix + cp.async, no padding.
// 3-stage cp.async ring, wait_group 1. Stage 32KB -> 96KB -> 2 CTAs/SM.
// Output: fp32 C (Cf != nullptr) or bf16 hi/lo planes (Ch, Cl).
// ---------------------------------------------------------------------------
#define ROWH 64                      // halves per smem row (hi 32 + lo 32)
#define B_OFF (128 * ROWH)           // B region offset in halves (8192)
#define STAGE_H (2 * 128 * ROWH)     // stage halves (16384) = 32768 B
#define GSTAGES 3
#define GEMM_SMEM_BYTES (GSTAGES * STAGE_H * 2)   // 98304

__global__ __launch_bounds__(256) void gemm_planes_bias_kernel(
    const __nv_bfloat16* __restrict__ Ah, const __nv_bfloat16* __restrict__ Al,
    const __nv_bfloat16* __restrict__ Bh, const __nv_bfloat16* __restrict__ Bl,
    const float* __restrict__ bias,
    float* __restrict__ Cf,
    __nv_bfloat16* __restrict__ Ch, __nv_bfloat16* __restrict__ Cl,
    int M, int N, int K)
{
    extern __shared__ __nv_bfloat16 sm[];
    const unsigned sb = (unsigned)__cvta_generic_to_shared(sm);

    const int t = threadIdx.x, lane = t & 31, wid = t >> 5;
    const int bm = blockIdx.y, bn = blockIdx.x;
    const int warp_m = wid >> 1, warp_n = wid & 1;   // 4 x 2

    // cp.async: one row per thread-half; t&127 = row, t>>7 = chunk pair
    const int ar = t & 127;
    const int ac = t >> 7;           // 0 or 1 -> k-halves 16*ac
    const __nv_bfloat16* Ahg = Ah + (size_t)(bm * 128 + ar) * K + ac * 16;
    const __nv_bfloat16* Alg = Al + (size_t)(bm * 128 + ar) * K + ac * 16;
    const __nv_bfloat16* Bhg = Bh + (size_t)(bn * 128 + ar) * K + ac * 16;
    const __nv_bfloat16* Blg = Bl + (size_t)(bn * 128 + ar) * K + ac * 16;

    // Swizzled smem chunk positions (halves) for this thread's 8 chunks
    const int rsw = ar & 7;
    const unsigned sAh0 = 2 * (ar * ROWH + (((2 * ac + 0) ^ rsw)) * 8);
    const unsigned sAh1 = 2 * (ar * ROWH + (((2 * ac + 1) ^ rsw)) * 8);
    const unsigned sAl0 = 2 * (ar * ROWH + (((4 + 2 * ac + 0) ^ rsw)) * 8);
    const unsigned sAl1 = 2 * (ar * ROWH + (((4 + 2 * ac + 1) ^ rsw)) * 8);

    float c[2][8][4];
    #pragma unroll
    for (int mf = 0; mf < 2; mf++)
        #pragma unroll
        for (int nf = 0; nf < 8; nf++)
            #pragma unroll
            for (int i = 0; i < 4; i++) c[mf][nf][i] = 0.f;

    const int nK = K / 32;

    auto issue_stage = [&](int kt) {
        const int go = kt * 32;
        const unsigned d = sb + 2 * (kt % GSTAGES) * STAGE_H;
        cpa16(d + sAh0,                 Ahg + go);
        cpa16(d + sAh1,                 Ahg + go + 8);
        cpa16(d + sAl0,                 Alg + go);
        cpa16(d + sAl1,                 Alg + go + 8);
        cpa16(d + 2 * B_OFF + sAh0,     Bhg + go);
        cpa16(d + 2 * B_OFF + sAh1,     Bhg + go + 8);
        cpa16(d + 2 * B_OFF + sAl0,     Blg + go);
        cpa16(d + 2 * B_OFF + sAl1,     Blg + go + 8);
        asm volatile("cp.async.commit_group;\n" ::: "memory");
    };

    issue_stage(0);
    issue_stage(1);

    for (int kt = 0; kt < nK; kt++) {
        asm volatile("cp.async.wait_group 1;\n" ::: "memory");
        __syncthreads();

        if (kt + 2 < nK) issue_stage(kt + 2);

        const unsigned base = sb + 2 * (kt % GSTAGES) * STAGE_H;
        #pragma unroll
        for (int s = 0; s < 2; s++) {
            unsigned ah[2][4], al[2][4];
            #pragma unroll
            for (int mf = 0; mf < 2; mf++) {
                const int row = warp_m * 32 + mf * 16 + (lane & 15);
                const int ch  = 2 * s + (lane >> 4);
                const unsigned a = base
                    + 2 * (row * ROWH + ((ch ^ (row & 7)) * 8));
                const unsigned b = base
                    + 2 * (row * ROWH + (((4 + ch) ^ (row & 7)) * 8));
                ldsm_x4(ah[mf][0], ah[mf][1], ah[mf][2], ah[mf][3], a);
                ldsm_x4(al[mf][0], al[mf][1], al[mf][2], al[mf][3], b);
            }
            #pragma unroll
            for (int nfp = 0; nfp < 4; nfp++) {
                const int nrow = warp_n * 64 + nfp * 16 + (lane & 7) + 8 * (lane >> 4);
                const int ch   = 2 * s + ((lane >> 3) & 1);
                const unsigned a = base
                    + 2 * (B_OFF + nrow * ROWH + ((ch ^ (nrow & 7)) * 8));
                const unsigned b = base
                    + 2 * (B_OFF + nrow * ROWH + (((4 + ch) ^ (nrow & 7)) * 8));
                unsigned bh0, bh1, bh2, bh3, bl0, bl1, bl2, bl3;
                ldsm_x4(bh0, bh1, bh2, bh3, a);
                ldsm_x4(bl0, bl1, bl2, bl3, b);
                #pragma unroll
                for (int mf = 0; mf < 2; mf++) {
                    float* c0 = c[mf][2 * nfp];
                    float* c1 = c[mf][2 * nfp + 1];
                    mma_bf16(c0[0], c0[1], c0[2], c0[3],
                             ah[mf][0], ah[mf][1], ah[mf][2], ah[mf][3], bh0, bh1);
                    mma_bf16(c0[0], c0[1], c0[2], c0[3],
                             al[mf][0], al[mf][1], al[mf][2], al[mf][3], bh0, bh1);
                    mma_bf16(c0[0], c0[1], c0[2], c0[3],
                             ah[mf][0], ah[mf][1], ah[mf][2], ah[mf][3], bl0, bl1);
                    mma_bf16(c1[0], c1[1], c1[2], c1[3],
                             ah[mf][0], ah[mf][1], ah[mf][2], ah[mf][3], bh2, bh3);
                    mma_bf16(c1[0], c1[1], c1[2], c1[3],
                             al[mf][0], al[mf][1], al[mf][2], al[mf][3], bh2, bh3);
                    mma_bf16(c1[0], c1[1], c1[2], c1[3],
                             ah[mf][0], ah[mf][1], ah[mf][2], ah[mf][3], bl2, bl3);
                }
            }
        }
    }

    // Epilogue
    const int g = lane >> 2, q = lane & 3;
    const int crow0 = bm * 128 + warp_m * 32 + g;
    const int ccol0 = bn * 128 + warp_n * 64 + 2 * q;
    if (Cf) {
        #pragma unroll
        for (int nf = 0; nf < 8; nf++) {
            const int col = ccol0 + nf * 8;
            const float bx = bias[col];
            const float by = bias[col + 1];
            #pragma unroll
            for (int mf = 0; mf < 2; mf++) {
                const int row = crow0 + mf * 16;
                *(float2*)(Cf + (size_t)row * N + col) =
                    make_float2(c[mf][nf][0] + bx, c[mf][nf][1] + by);
                *(float2*)(Cf + (size_t)(row + 8) * N + col) =
                    make_float2(c[mf][nf][2] + bx, c[mf][nf][3] + by);
            }
        }
    } else {
        unsigned* Chu = (unsigned*)Ch;
        unsigned* Clu = (unsigned*)Cl;
        const int nh = N / 2;
        #pragma unroll
        for (int nf = 0; nf < 8; nf++) {
            const int col = ccol0 + nf * 8;
            const float bx = bias[col];
            const float by = bias[col + 1];
            #pragma unroll
            for (int mf = 0; mf < 2; mf++) {
                const int row = crow0 + mf * 16;
                float v0 = c[mf][nf][0] + bx, v1 = c[mf][nf][1] + by;
                float w0 = c[mf][nf][2] + bx, w1 = c[mf][nf][3] + by;
                __nv_bfloat162 vh = __floats2bfloat162_rn(v0, v1);
                __nv_bfloat162 wh = __floats2bfloat162_rn(w0, w1);
                __nv_bfloat162 vl = __floats2bfloat162_rn(v0 - __low2float(vh),
                                                          v1 - __high2float(vh));
                __nv_bfloat162 wl = __floats2bfloat162_rn(w0 - __low2float(wh),
                                                          w1 - __high2float(wh));
                Chu[(size_t)row * nh + col / 2]       = bf2u(vh);
                Clu[(size_t)row * nh + col / 2]       = bf2u(vl);
                Chu[(size_t)(row + 8) * nh + col / 2] = bf2u(wh);
                Clu[(size_t)(row + 8) * nh + col / 2] = bf2u(wl);
            }
        }
    }
}

// ---------------------------------------------------------------------------
// Tensor-core flash attention (causal), triple-bf16. Plane in, plane out.
// ---------------------------------------------------------------------------
#define ATT_C 0.12751666769323707f  // (1/sqrt(128)) * log2(e)
#define RSTR  136
#define QH_OFF 0
#define QL_OFF 17408
#define KH_OFF 34816
#define KL_OFF 43520
#define VH_OFF 52224
#define VL_OFF 60928
#define ATT_SMEM_BYTES (69632 * 2)

__global__ __launch_bounds__(256) void flash_attn_tc_kernel(
    const __nv_bfloat16* __restrict__ qkvh, const __nv_bfloat16* __restrict__ qkvl,
    __nv_bfloat16* __restrict__ outh, __nv_bfloat16* __restrict__ outl)
{
    extern __shared__ unsigned smu[];
    const unsigned sbase = (unsigned)__cvta_generic_to_shared(smu);

    const int qblk = blockIdx.x;
    const int h    = blockIdx.y;
    const int b    = blockIdx.z;
    const int tid  = threadIdx.x;
    const int lane = tid & 31;
    const int w    = tid >> 5;
    const int g    = lane >> 2;
    const int q    = lane & 3;

    {
        const int r  = tid >> 1;
        const int c0 = (tid & 1) * 64;
        const size_t gofs = (size_t)(b * SEQ + qblk * 128 + r) * DM3 + h * DHEAD + c0;
        const uint4* qhp = (const uint4*)(qkvh + gofs);
        const uint4* qlp = (const uint4*)(qkvl + gofs);
        #pragma unroll
        for (int i = 0; i < 8; i++) {
            const int hofs = r * RSTR + c0 + 8 * i;
            *(uint4*)(smu + (QH_OFF + hofs) / 2) = qhp[i];
            *(uint4*)(smu + (QL_OFF + hofs) / 2) = qlp[i];
        }
    }
    __syncthreads();

    unsigned qh[8][4], ql[8][4];
    {
        const int row = 16 * w + (lane & 15);
        const int cb  = 8 * (lane >> 4);
        #pragma unroll
        for (int ds = 0; ds < 8; ds++) {
            unsigned a = sbase + 2 * (QH_OFF + row * RSTR + 16 * ds + cb);
            ldsm_x4(qh[ds][0], qh[ds][1], qh[ds][2], qh[ds][3], a);
            ldsm_x4(ql[ds][0], ql[ds][1], ql[ds][2], ql[ds][3],
                    a + 2 * (QL_OFF - QH_OFF));
        }
    }

    float o[16][4];
    #pragma unroll
    for (int nf = 0; nf < 16; nf++)
        #pragma unroll
        for (int i = 0; i < 4; i++) o[nf][i] = 0.f;
    float m0 = -1e30f, m1 = -1e30f, l0 = 0.f, l1 = 0.f;

    const int ntiles = 2 * qblk + 2;
    const int warp_row_max = qblk * 128 + 16 * w + 15;

    for (int kt = 0; kt < ntiles; kt++) {
        __syncthreads();
        {
            const int r  = tid >> 2;
            const int c0 = (tid & 3) * 32;
            const size_t kofs = (size_t)(b * SEQ + kt * 64 + r) * DM3
                                + h * DHEAD + DMODEL + c0;
            const uint4* khp = (const uint4*)(qkvh + kofs);
            const uint4* klp = (const uint4*)(qkvl + kofs);
            const uint4* vhp = (const uint4*)(qkvh + kofs + DMODEL);
            const uint4* vlp = (const uint4*)(qkvl + kofs + DMODEL);
            #pragma unroll
            for (int i = 0; i < 4; i++) {
                const int hofs = r * RSTR + c0 + 8 * i;
                *(uint4*)(smu + (KH_OFF + hofs) / 2) = khp[i];
                *(uint4*)(smu + (KL_OFF + hofs) / 2) = klp[i];
                *(uint4*)(smu + (VH_OFF + hofs) / 2) = vhp[i];
                *(uint4*)(smu + (VL_OFF + hofs) / 2) = vlp[i];
            }
        }
        __syncthreads();

        if (kt * 64 > warp_row_max) continue;

        float s[8][4];
        #pragma unroll
        for (int nf = 0; nf < 8; nf++)
            #pragma unroll
            for (int i = 0; i < 4; i++) s[nf][i] = 0.f;

        {
            const int krow   = (lane & 7) + 8 * (lane >> 4);
            const int kchunk = 8 * ((lane >> 3) & 1);
            #pragma unroll
            for (int ds = 0; ds < 8; ds++) {
                #pragma unroll
                for (int nfp = 0; nfp < 4; nfp++) {
                    unsigned a = sbase + 2 * (KH_OFF + (16 * nfp + krow) * RSTR
                                              + 16 * ds + kchunk);
                    unsigned bh0, bh1, bh2, bh3, bl0, bl1, bl2, bl3;
                    ldsm_x4(bh0, bh1, bh2, bh3, a);
                    ldsm_x4(bl0, bl1, bl2, bl3, a + 2 * (KL_OFF - KH_OFF));
                    float* s0 = s[2 * nfp];
                    float* s1 = s[2 * nfp + 1];
                    mma_bf16(s0[0], s0[1], s0[2], s0[3],
                             qh[ds][0], qh[ds][1], qh[ds][2], qh[ds][3], bh0, bh1);
                    mma_bf16(s0[0], s0[1], s0[2], s0[3],
                             ql[ds][0], ql[ds][1], ql[ds][2], ql[ds][3], bh0, bh1);
                    mma_bf16(s0[0], s0[1], s0[2], s0[3],
                             qh[ds][0], qh[ds][1], qh[ds][2], qh[ds][3], bl0, bl1);
                    mma_bf16(s1[0], s1[1], s1[2], s1[3],
                             qh[ds][0], qh[ds][1], qh[ds][2], qh[ds][3], bh2, bh3);
                    mma_bf16(s1[0], s1[1], s1[2], s1[3],
                             ql[ds][0], ql[ds][1], ql[ds][2], ql[ds][3], bh2, bh3);
                    mma_bf16(s1[0], s1[1], s1[2], s1[3],
                             qh[ds][0], qh[ds][1], qh[ds][2], qh[ds][3], bl2, bl3);
                }
            }
        }

        if (kt >= 2 * qblk) {
            const int row0 = qblk * 128 + 16 * w + g;
            #pragma unroll
            for (int nf = 0; nf < 8; nf++) {
                const int col = kt * 64 + 8 * nf + 2 * q;
                if (col     > row0)     s[nf][0] = -CUDART_INF_F;
                if (col + 1 > row0)     s[nf][1] = -CUDART_INF_F;
                if (col     > row0 + 8) s[nf][2] = -CUDART_INF_F;
                if (col + 1 > row0 + 8) s[nf][3] = -CUDART_INF_F;
            }
        }

        float tm0 = -CUDART_INF_F, tm1 = -CUDART_INF_F;
        #pragma unroll
        for (int nf = 0; nf < 8; nf++) {
            tm0 = fmaxf(tm0, fmaxf(s[nf][0], s[nf][1]));
            tm1 = fmaxf(tm1, fmaxf(s[nf][2], s[nf][3]));
        }
        tm0 = fmaxf(tm0, __shfl_xor_sync(0xffffffffu, tm0, 1));
        tm0 = fmaxf(tm0, __shfl_xor_sync(0xffffffffu, tm0, 2));
        tm1 = fmaxf(tm1, __shfl_xor_sync(0xffffffffu, tm1, 1));
        tm1 = fmaxf(tm1, __shfl_xor_sync(0xffffffffu, tm1, 2));

        const float m0n = fmaxf(m0, tm0);
        const float m1n = fmaxf(m1, tm1);
        const float cr0 = exp2f((m0 - m0n) * ATT_C);
        const float cr1 = exp2f((m1 - m1n) * ATT_C);
        m0 = m0n; m1 = m1n;
        l0 *= cr0; l1 *= cr1;
        #pragma unroll
        for (int nf = 0; nf < 16; nf++) {
            o[nf][0] *= cr0; o[nf][1] *= cr0;
            o[nf][2] *= cr1; o[nf][3] *= cr1;
        }

        unsigned ph[8][2], pl[8][2];
        #pragma unroll
        for (int nf = 0; nf < 8; nf++) {
            float p0 = exp2f((s[nf][0] - m0) * ATT_C);
            float p1 = exp2f((s[nf][1] - m0) * ATT_C);
            float p2 = exp2f((s[nf][2] - m1) * ATT_C);
            float p3 = exp2f((s[nf][3] - m1) * ATT_C);
            l0 += p0 + p1;
            l1 += p2 + p3;
            __nv_bfloat162 h01 = __floats2bfloat162_rn(p0, p1);
            __nv_bfloat162 h23 = __floats2bfloat162_rn(p2, p3);
            __nv_bfloat162 e01 = __floats2bfloat162_rn(p0 - __low2float(h01),
                                                       p1 - __high2float(h01));
            __nv_bfloat162 e23 = __floats2bfloat162_rn(p2 - __low2float(h23),
                                                       p3 - __high2float(h23));
            ph[nf][0] = bf2u(h01); ph[nf][1] = bf2u(h23);
            pl[nf][0] = bf2u(e01); pl[nf][1] = bf2u(e23);
        }

        {
            const int vrow   = (lane & 15);
            const int vchunk = 8 * (lane >> 4);
            #pragma unroll
            for (int j = 0; j < 4; j++) {
                const unsigned ah0 = ph[2 * j][0],     ah1 = ph[2 * j][1];
                const unsigned ah2 = ph[2 * j + 1][0], ah3 = ph[2 * j + 1][1];
                const unsigned al0 = pl[2 * j][0],     al1 = pl[2 * j][1];
                const unsigned al2 = pl[2 * j + 1][0], al3 = pl[2 * j + 1][1];
                #pragma unroll
                for (int nfp = 0; nfp < 8; nfp++) {
                    unsigned a = sbase + 2 * (VH_OFF + (16 * j + vrow) * RSTR
                                              + 16 * nfp + vchunk);
                    unsigned vh0, vh1, vh2, vh3, vl0, vl1, vl2, vl3;
                    ldsm_x4t(vh0, vh1, vh2, vh3, a);
                    ldsm_x4t(vl0, vl1, vl2, vl3, a + 2 * (VL_OFF - VH_OFF));
                    float* o0 = o[2 * nfp];
                    float* o1 = o[2 * nfp + 1];
                    mma_bf16(o0[0], o0[1], o0[2], o0[3], ah0, ah1, ah2, ah3, vh0, vh1);
                    mma_bf16(o0[0], o0[1], o0[2], o0[3], al0, al1, al2, al3, vh0, vh1);
                    mma_bf16(o0[0], o0[1], o0[2], o0[3], ah0, ah1, ah2, ah3, vl0, vl1);
                    mma_bf16(o1[0], o1[1], o1[2], o1[3], ah0, ah1, ah2, ah3, vh2, vh3);
                    mma_bf16(o1[0], o1[1], o1[2], o1[3], al0, al1, al2, al3, vh2, vh3);
                    mma_bf16(o1[0], o1[1], o1[2], o1[3], ah0, ah1, ah2, ah3, vl2, vl3);
                }
            }
        }
    }

    l0 += __shfl_xor_sync(0xffffffffu, l0, 1);
    l0 += __shfl_xor_sync(0xffffffffu, l0, 2);
    l1 += __shfl_xor_sync(0xffffffffu, l1, 1);
    l1 += __shfl_xor_sync(0xffffffffu, l1, 2);
    const float inv0 = 1.f / l0;
    const float inv1 = 1.f / l1;

    const size_t row0 = (size_t)(b * SEQ + qblk * 128 + 16 * w + g);
    unsigned* obh = (unsigned*)(outh + row0 * DMODEL + h * DHEAD);
    unsigned* obl = (unsigned*)(outl + row0 * DMODEL + h * DHEAD);
    #pragma unroll
    for (int nf = 0; nf < 16; nf++) {
        const int ci = 4 * nf + q;
        float x0 = o[nf][0] * inv0, x1 = o[nf][1] * inv0;
        float y0 = o[nf][2] * inv1, y1 = o[nf][3] * inv1;
        __nv_bfloat162 xh = __floats2bfloat162_rn(x0, x1);
        __nv_bfloat162 yh = __floats2bfloat162_rn(y0, y1);
        __nv_bfloat162 xl = __floats2bfloat162_rn(x0 - __low2float(xh),
                                                  x1 - __high2float(xh));
        __nv_bfloat162 yl = __floats2bfloat162_rn(y0 - __low2float(yh),
                                                  y1 - __high2float(yh));
        obh[ci] = bf2u(xh);
        obl[ci] = bf2u(xl);
        obh[ci + 4 * DMODEL] = bf2u(yh);
        obl[ci + 4 * DMODEL] = bf2u(yl);
    }
}

// ---------------------------------------------------------------------------
// kernel_launch
// ---------------------------------------------------------------------------
extern "C" void kernel_launch(void* const* d_in, const int* in_sizes, int n_in,
                              void* d_out, int out_size)
{
    const float* x     = (const float*)d_in[0];
    const float* W_qkv = (const float*)d_in[1];
    const float* b_qkv = (const float*)d_in[2];
    const float* W_out = (const float*)d_in[3];
    const float* b_out = (const float*)d_in[4];
    float* out = (float*)d_out;

    __nv_bfloat16 *qh, *ql, *xh, *xl, *wqh, *wql, *woh, *wol, *ath, *atl;
    cudaGetSymbolAddress((void**)&qh,  g_qkvh);
    cudaGetSymbolAddress((void**)&ql,  g_qkvl);
    cudaGetSymbolAddress((void**)&xh,  g_xh);
    cudaGetSymbolAddress((void**)&xl,  g_xl);
    cudaGetSymbolAddress((void**)&wqh, g_wqkvth);
    cudaGetSymbolAddress((void**)&wql, g_wqkvtl);
    cudaGetSymbolAddress((void**)&woh, g_woutth);
    cudaGetSymbolAddress((void**)&wol, g_wouttl);
    cudaGetSymbolAddress((void**)&ath, g_attnh);
    cudaGetSymbolAddress((void**)&atl, g_attnl);

    cudaFuncSetAttribute(flash_attn_tc_kernel,
                         cudaFuncAttributeMaxDynamicSharedMemorySize,
                         ATT_SMEM_BYTES);
    cudaFuncSetAttribute(gemm_planes_bias_kernel,
                         cudaFuncAttributeMaxDynamicSharedMemorySize,
                         GEMM_SMEM_BYTES);

    // Prep
    split_rm_kernel<<<(MTOT * DMODEL / 4 + 255) / 256, 256>>>(
        (const float4*)x, (uint2*)xh, (uint2*)xl, MTOT * DMODEL / 4);
    split_tr_kernel<<<dim3(DM3 / 32, DMODEL / 32), 256>>>(
        W_qkv, wqh, wql, DMODEL, DM3);
    split_tr_kernel<<<dim3(DMODEL / 32, DMODEL / 32), 256>>>(
        W_out, woh, wol, DMODEL, DMODEL);

    // 1) QKV GEMM -> bf16 hi/lo planes
    gemm_planes_bias_kernel<<<dim3(DM3 / 128, MTOT / 128), 256, GEMM_SMEM_BYTES>>>(
        xh, xl, wqh, wql, b_qkv, nullptr, qh, ql, MTOT, DM3, DMODEL);

    // 2) Flash attention (plane inputs) -> bf16 hi/lo planes
    flash_attn_tc_kernel<<<dim3(16, NHEADS, BATCH), 256, ATT_SMEM_BYTES>>>(
        qh, ql, ath, atl);

    // 3) Output GEMM -> fp32
    gemm_planes_bias_kernel<<<dim3(DMODEL / 128, MTOT / 128), 256, GEMM_SMEM_BYTES>>>(
        ath, atl, woh, wol, b_out, out, nullptr, nullptr, MTOT, DMODEL, DMODEL);
}

// round 10
// speedup vs baseline: 1.0895x; 1.0895x over previous
#include <cuda_runtime.h>
#include <cuda_bf16.h>
#include <math_constants.h>

#define BATCH   2
#define SEQ     2048
#define NHEADS  16
#define DHEAD   128
#define DMODEL  2048
#define DM3     6144
#define MTOT    4096

// Scratch (device globals)
__device__ __nv_bfloat16 g_qkvh[(size_t)MTOT * DM3];
__device__ __nv_bfloat16 g_qkvl[(size_t)MTOT * DM3];
__device__ __nv_bfloat16 g_xh[(size_t)MTOT * DMODEL];
__device__ __nv_bfloat16 g_xl[(size_t)MTOT * DMODEL];
__device__ __nv_bfloat16 g_wqkvth[(size_t)DM3 * DMODEL];   // [N=6144][K=2048]
__device__ __nv_bfloat16 g_wqkvtl[(size_t)DM3 * DMODEL];
__device__ __nv_bfloat16 g_woutth[(size_t)DMODEL * DMODEL];
__device__ __nv_bfloat16 g_wouttl[(size_t)DMODEL * DMODEL];
__device__ __nv_bfloat16 g_attnh[(size_t)MTOT * DMODEL];
__device__ __nv_bfloat16 g_attnl[(size_t)MTOT * DMODEL];

// ---------------------------------------------------------------------------
// Helpers
// ---------------------------------------------------------------------------
static __device__ __forceinline__ void mma_bf16(
    float& c0, float& c1, float& c2, float& c3,
    unsigned a0, unsigned a1, unsigned a2, unsigned a3,
    unsigned b0, unsigned b1)
{
    asm volatile(
        "mma.sync.aligned.m16n8k16.row.col.f32.bf16.bf16.f32 "
        "{%0,%1,%2,%3}, {%4,%5,%6,%7}, {%8,%9}, {%0,%1,%2,%3};\n"
        : "+f"(c0), "+f"(c1), "+f"(c2), "+f"(c3)
        : "r"(a0), "r"(a1), "r"(a2), "r"(a3), "r"(b0), "r"(b1));
}
static __device__ __forceinline__ void ldsm_x4(
    unsigned& r0, unsigned& r1, unsigned& r2, unsigned& r3, unsigned addr)
{
    asm volatile("ldmatrix.sync.aligned.m8n8.x4.shared.b16 {%0,%1,%2,%3}, [%4];\n"
                 : "=r"(r0), "=r"(r1), "=r"(r2), "=r"(r3) : "r"(addr));
}
static __device__ __forceinline__ void ldsm_x4t(
    unsigned& r0, unsigned& r1, unsigned& r2, unsigned& r3, unsigned addr)
{
    asm volatile("ldmatrix.sync.aligned.m8n8.x4.trans.shared.b16 {%0,%1,%2,%3}, [%4];\n"
                 : "=r"(r0), "=r"(r1), "=r"(r2), "=r"(r3) : "r"(addr));
}
static __device__ __forceinline__ unsigned bf2u(__nv_bfloat162 v) {
    return *reinterpret_cast<unsigned*>(&v);
}
static __device__ __forceinline__ void split4(float4 f, uint2& hi, uint2& lo) {
    __nv_bfloat162 h0 = __floats2bfloat162_rn(f.x, f.y);
    __nv_bfloat162 h1 = __floats2bfloat162_rn(f.z, f.w);
    float hx = __low2float(h0), hy = __high2float(h0);
    float hz = __low2float(h1), hw = __high2float(h1);
    __nv_bfloat162 l0 = __floats2bfloat162_rn(f.x - hx, f.y - hy);
    __nv_bfloat162 l1 = __floats2bfloat162_rn(f.z - hz, f.w - hw);
    hi.x = bf2u(h0); hi.y = bf2u(h1);
    lo.x = bf2u(l0); lo.y = bf2u(l1);
}
static __device__ __forceinline__ void cpa16(unsigned saddr, const void* g) {
    asm volatile("cp.async.cg.shared.global [%0], [%1], 16;\n"
                 :: "r"(saddr), "l"(g));
}

// ---------------------------------------------------------------------------
// Prep kernels: fp32 -> bf16 hi/lo planes
// ---------------------------------------------------------------------------
__global__ __launch_bounds__(256) void split_rm_kernel(
    const float4* __restrict__ src, uint2* __restrict__ h, uint2* __restrict__ l,
    int n4)
{
    int i = blockIdx.x * 256 + threadIdx.x;
    if (i < n4) {
        uint2 hi, lo;
        split4(src[i], hi, lo);
        h[i] = hi; l[i] = lo;
    }
}

// W [K][N] fp32 -> Wt hi/lo [N][K] bf16
__global__ __launch_bounds__(256) void split_tr_kernel(
    const float* __restrict__ W,
    __nv_bfloat16* __restrict__ th, __nv_bfloat16* __restrict__ tl,
    int K, int N)
{
    __shared__ float tile[32][33];
    const int n0 = blockIdx.x * 32, k0 = blockIdx.y * 32;
    const int tx = threadIdx.x & 31, ty = threadIdx.x >> 5;  // 32 x 8
    #pragma unroll
    for (int i = 0; i < 32; i += 8)
        tile[ty + i][tx] = W[(size_t)(k0 + ty + i) * N + (n0 + tx)];
    __syncthreads();
    #pragma unroll
    for (int i = 0; i < 32; i += 8) {
        float v = tile[tx][ty + i];
        __nv_bfloat16 hb = __float2bfloat16(v);
        __nv_bfloat16 lb = __float2bfloat16(v - __bfloat162float(hb));
        size_t o = (size_t)(n0 + ty + i) * K + (k0 + tx);
        th[o] = hb; tl[o] = lb;
    }
}

// ---------------------------------------------------------------------------
// Plane GEMM: C = (Ah+Al)[M,K] @ (Bh+Bl)^T[N,K] + bias
// Block 128x128, ktile 32, 256 threads = 8 warps (4m x 2n), warp tile 32x64.
// Smem: per tile row 128B = 8 chunks of 16B: [4 hi | 4 lo], position
// swizzled chunk^(row&7) -> conflict-free ldmatrix + cp.async, no padding.
// 3-stage cp.async ring, wait_group 1. Stage 32KB -> 96KB.
// __launch_bounds__(256, 2) pins regs <= 128 so 2 CTAs co-reside per SM.
// Output: fp32 C (Cf != nullptr) or bf16 hi/lo planes (Ch, Cl).
// ---------------------------------------------------------------------------
#define ROWH 64                      // halves per smem row (hi 32 + lo 32)
#define B_OFF (128 * ROWH)           // B region offset in halves (8192)
#define STAGE_H (2 * 128 * ROWH)     // stage halves (16384) = 32768 B
#define GSTAGES 3
#define GEMM_SMEM_BYTES (GSTAGES * STAGE_H * 2)   // 98304

__global__ __launch_bounds__(256, 2) void gemm_planes_bias_kernel(
    const __nv_bfloat16* __restrict__ Ah, const __nv_bfloat16* __restrict__ Al,
    const __nv_bfloat16* __restrict__ Bh, const __nv_bfloat16* __restrict__ Bl,
    const float* __restrict__ bias,
    float* __restrict__ Cf,
    __nv_bfloat16* __restrict__ Ch, __nv_bfloat16* __restrict__ Cl,
    int M, int N, int K)
{
    extern __shared__ __nv_bfloat16 sm[];
    const unsigned sb = (unsigned)__cvta_generic_to_shared(sm);

    const int t = threadIdx.x, lane = t & 31, wid = t >> 5;
    const int bm = blockIdx.y, bn = blockIdx.x;
    const int warp_m = wid >> 1, warp_n = wid & 1;   // 4 x 2

    // cp.async: one row per thread-half; t&127 = row, t>>7 = chunk pair
    const int ar = t & 127;
    const int ac = t >> 7;           // 0 or 1 -> k-halves 16*ac
    const __nv_bfloat16* Ahg = Ah + (size_t)(bm * 128 + ar) * K + ac * 16;
    const __nv_bfloat16* Alg = Al + (size_t)(bm * 128 + ar) * K + ac * 16;
    const __nv_bfloat16* Bhg = Bh + (size_t)(bn * 128 + ar) * K + ac * 16;
    const __nv_bfloat16* Blg = Bl + (size_t)(bn * 128 + ar) * K + ac * 16;

    // Swizzled smem chunk positions (halves) for this thread's 8 chunks
    const int rsw = ar & 7;
    const unsigned sAh0 = 2 * (ar * ROWH + (((2 * ac + 0) ^ rsw)) * 8);
    const unsigned sAh1 = 2 * (ar * ROWH + (((2 * ac + 1) ^ rsw)) * 8);
    const unsigned sAl0 = 2 * (ar * ROWH + (((4 + 2 * ac + 0) ^ rsw)) * 8);
    const unsigned sAl1 = 2 * (ar * ROWH + (((4 + 2 * ac + 1) ^ rsw)) * 8);

    float c[2][8][4];
    #pragma unroll
    for (int mf = 0; mf < 2; mf++)
        #pragma unroll
        for (int nf = 0; nf < 8; nf++)
            #pragma unroll
            for (int i = 0; i < 4; i++) c[mf][nf][i] = 0.f;

    const int nK = K / 32;

    auto issue_stage = [&](int kt) {
        const int go = kt * 32;
        const unsigned d = sb + 2 * (kt % GSTAGES) * STAGE_H;
        cpa16(d + sAh0,                 Ahg + go);
        cpa16(d + sAh1,                 Ahg + go + 8);
        cpa16(d + sAl0,                 Alg + go);
        cpa16(d + sAl1,                 Alg + go + 8);
        cpa16(d + 2 * B_OFF + sAh0,     Bhg + go);
        cpa16(d + 2 * B_OFF + sAh1,     Bhg + go + 8);
        cpa16(d + 2 * B_OFF + sAl0,     Blg + go);
        cpa16(d + 2 * B_OFF + sAl1,     Blg + go + 8);
        asm volatile("cp.async.commit_group;\n" ::: "memory");
    };

    issue_stage(0);
    issue_stage(1);

    for (int kt = 0; kt < nK; kt++) {
        asm volatile("cp.async.wait_group 1;\n" ::: "memory");
        __syncthreads();

        if (kt + 2 < nK) issue_stage(kt + 2);

        const unsigned base = sb + 2 * (kt % GSTAGES) * STAGE_H;
        #pragma unroll
        for (int s = 0; s < 2; s++) {
            unsigned ah[2][4], al[2][4];
            #pragma unroll
            for (int mf = 0; mf < 2; mf++) {
                const int row = warp_m * 32 + mf * 16 + (lane & 15);
                const int ch  = 2 * s + (lane >> 4);
                const unsigned a = base
                    + 2 * (row * ROWH + ((ch ^ (row & 7)) * 8));
                const unsigned b = base
                    + 2 * (row * ROWH + (((4 + ch) ^ (row & 7)) * 8));
                ldsm_x4(ah[mf][0], ah[mf][1], ah[mf][2], ah[mf][3], a);
                ldsm_x4(al[mf][0], al[mf][1], al[mf][2], al[mf][3], b);
            }
            #pragma unroll
            for (int nfp = 0; nfp < 4; nfp++) {
                const int nrow = warp_n * 64 + nfp * 16 + (lane & 7) + 8 * (lane >> 4);
                const int ch   = 2 * s + ((lane >> 3) & 1);
                const unsigned a = base
                    + 2 * (B_OFF + nrow * ROWH + ((ch ^ (nrow & 7)) * 8));
                const unsigned b = base
                    + 2 * (B_OFF + nrow * ROWH + (((4 + ch) ^ (nrow & 7)) * 8));
                unsigned bh0, bh1, bh2, bh3, bl0, bl1, bl2, bl3;
                ldsm_x4(bh0, bh1, bh2, bh3, a);
                ldsm_x4(bl0, bl1, bl2, bl3, b);
                #pragma unroll
                for (int mf = 0; mf < 2; mf++) {
                    float* c0 = c[mf][2 * nfp];
                    float* c1 = c[mf][2 * nfp + 1];
                    mma_bf16(c0[0], c0[1], c0[2], c0[3],
                             ah[mf][0], ah[mf][1], ah[mf][2], ah[mf][3], bh0, bh1);
                    mma_bf16(c0[0], c0[1], c0[2], c0[3],
                             al[mf][0], al[mf][1], al[mf][2], al[mf][3], bh0, bh1);
                    mma_bf16(c0[0], c0[1], c0[2], c0[3],
                             ah[mf][0], ah[mf][1], ah[mf][2], ah[mf][3], bl0, bl1);
                    mma_bf16(c1[0], c1[1], c1[2], c1[3],
                             ah[mf][0], ah[mf][1], ah[mf][2], ah[mf][3], bh2, bh3);
                    mma_bf16(c1[0], c1[1], c1[2], c1[3],
                             al[mf][0], al[mf][1], al[mf][2], al[mf][3], bh2, bh3);
                    mma_bf16(c1[0], c1[1], c1[2], c1[3],
                             ah[mf][0], ah[mf][1], ah[mf][2], ah[mf][3], bl2, bl3);
                }
            }
        }
    }

    // Epilogue
    const int g = lane >> 2, q = lane & 3;
    const int crow0 = bm * 128 + warp_m * 32 + g;
    const int ccol0 = bn * 128 + warp_n * 64 + 2 * q;
    if (Cf) {
        #pragma unroll
        for (int nf = 0; nf < 8; nf++) {
            const int col = ccol0 + nf * 8;
            const float bx = bias[col];
            const float by = bias[col + 1];
            #pragma unroll
            for (int mf = 0; mf < 2; mf++) {
                const int row = crow0 + mf * 16;
                *(float2*)(Cf + (size_t)row * N + col) =
                    make_float2(c[mf][nf][0] + bx, c[mf][nf][1] + by);
                *(float2*)(Cf + (size_t)(row + 8) * N + col) =
                    make_float2(c[mf][nf][2] + bx, c[mf][nf][3] + by);
            }
        }
    } else {
        unsigned* Chu = (unsigned*)Ch;
        unsigned* Clu = (unsigned*)Cl;
        const int nh = N / 2;
        #pragma unroll
        for (int nf = 0; nf < 8; nf++) {
            const int col = ccol0 + nf * 8;
            const float bx = bias[col];
            const float by = bias[col + 1];
            #pragma unroll
            for (int mf = 0; mf < 2; mf++) {
                const int row = crow0 + mf * 16;
                float v0 = c[mf][nf][0] + bx, v1 = c[mf][nf][1] + by;
                float w0 = c[mf][nf][2] + bx, w1 = c[mf][nf][3] + by;
                __nv_bfloat162 vh = __floats2bfloat162_rn(v0, v1);
                __nv_bfloat162 wh = __floats2bfloat162_rn(w0, w1);
                __nv_bfloat162 vl = __floats2bfloat162_rn(v0 - __low2float(vh),
                                                          v1 - __high2float(vh));
                __nv_bfloat162 wl = __floats2bfloat162_rn(w0 - __low2float(wh),
                                                          w1 - __high2float(wh));
                Chu[(size_t)row * nh + col / 2]       = bf2u(vh);
                Clu[(size_t)row * nh + col / 2]       = bf2u(vl);
                Chu[(size_t)(row + 8) * nh + col / 2] = bf2u(wh);
                Clu[(size_t)(row + 8) * nh + col / 2] = bf2u(wl);
            }
        }
    }
}

// ---------------------------------------------------------------------------
// Tensor-core flash attention (causal), triple-bf16. Plane in, plane out.
// ---------------------------------------------------------------------------
#define ATT_C 0.12751666769323707f  // (1/sqrt(128)) * log2(e)
#define RSTR  136
#define QH_OFF 0
#define QL_OFF 17408
#define KH_OFF 34816
#define KL_OFF 43520
#define VH_OFF 52224
#define VL_OFF 60928
#define ATT_SMEM_BYTES (69632 * 2)

__global__ __launch_bounds__(256) void flash_attn_tc_kernel(
    const __nv_bfloat16* __restrict__ qkvh, const __nv_bfloat16* __restrict__ qkvl,
    __nv_bfloat16* __restrict__ outh, __nv_bfloat16* __restrict__ outl)
{
    extern __shared__ unsigned smu[];
    const unsigned sbase = (unsigned)__cvta_generic_to_shared(smu);

    const int qblk = blockIdx.x;
    const int h    = blockIdx.y;
    const int b    = blockIdx.z;
    const int tid  = threadIdx.x;
    const int lane = tid & 31;
    const int w    = tid >> 5;
    const int g    = lane >> 2;
    const int q    = lane & 3;

    {
        const int r  = tid >> 1;
        const int c0 = (tid & 1) * 64;
        const size_t gofs = (size_t)(b * SEQ + qblk * 128 + r) * DM3 + h * DHEAD + c0;
        const uint4* qhp = (const uint4*)(qkvh + gofs);
        const uint4* qlp = (const uint4*)(qkvl + gofs);
        #pragma unroll
        for (int i = 0; i < 8; i++) {
            const int hofs = r * RSTR + c0 + 8 * i;
            *(uint4*)(smu + (QH_OFF + hofs) / 2) = qhp[i];
            *(uint4*)(smu + (QL_OFF + hofs) / 2) = qlp[i];
        }
    }
    __syncthreads();

    unsigned qh[8][4], ql[8][4];
    {
        const int row = 16 * w + (lane & 15);
        const int cb  = 8 * (lane >> 4);
        #pragma unroll
        for (int ds = 0; ds < 8; ds++) {
            unsigned a = sbase + 2 * (QH_OFF + row * RSTR + 16 * ds + cb);
            ldsm_x4(qh[ds][0], qh[ds][1], qh[ds][2], qh[ds][3], a);
            ldsm_x4(ql[ds][0], ql[ds][1], ql[ds][2], ql[ds][3],
                    a + 2 * (QL_OFF - QH_OFF));
        }
    }

    float o[16][4];
    #pragma unroll
    for (int nf = 0; nf < 16; nf++)
        #pragma unroll
        for (int i = 0; i < 4; i++) o[nf][i] = 0.f;
    float m0 = -1e30f, m1 = -1e30f, l0 = 0.f, l1 = 0.f;

    const int ntiles = 2 * qblk + 2;
    const int warp_row_max = qblk * 128 + 16 * w + 15;

    for (int kt = 0; kt < ntiles; kt++) {
        __syncthreads();
        {
            const int r  = tid >> 2;
            const int c0 = (tid & 3) * 32;
            const size_t kofs = (size_t)(b * SEQ + kt * 64 + r) * DM3
                                + h * DHEAD + DMODEL + c0;
            const uint4* khp = (const uint4*)(qkvh + kofs);
            const uint4* klp = (const uint4*)(qkvl + kofs);
            const uint4* vhp = (const uint4*)(qkvh + kofs + DMODEL);
            const uint4* vlp = (const uint4*)(qkvl + kofs + DMODEL);
            #pragma unroll
            for (int i = 0; i < 4; i++) {
                const int hofs = r * RSTR + c0 + 8 * i;
                *(uint4*)(smu + (KH_OFF + hofs) / 2) = khp[i];
                *(uint4*)(smu + (KL_OFF + hofs) / 2) = klp[i];
                *(uint4*)(smu + (VH_OFF + hofs) / 2) = vhp[i];
                *(uint4*)(smu + (VL_OFF + hofs) / 2) = vlp[i];
            }
        }
        __syncthreads();

        if (kt * 64 > warp_row_max) continue;

        float s[8][4];
        #pragma unroll
        for (int nf = 0; nf < 8; nf++)
            #pragma unroll
            for (int i = 0; i < 4; i++) s[nf][i] = 0.f;

        {
            const int krow   = (lane & 7) + 8 * (lane >> 4);
            const int kchunk = 8 * ((lane >> 3) & 1);
            #pragma unroll
            for (int ds = 0; ds < 8; ds++) {
                #pragma unroll
                for (int nfp = 0; nfp < 4; nfp++) {
                    unsigned a = sbase + 2 * (KH_OFF + (16 * nfp + krow) * RSTR
                                              + 16 * ds + kchunk);
                    unsigned bh0, bh1, bh2, bh3, bl0, bl1, bl2, bl3;
                    ldsm_x4(bh0, bh1, bh2, bh3, a);
                    ldsm_x4(bl0, bl1, bl2, bl3, a + 2 * (KL_OFF - KH_OFF));
                    float* s0 = s[2 * nfp];
                    float* s1 = s[2 * nfp + 1];
                    mma_bf16(s0[0], s0[1], s0[2], s0[3],
                             qh[ds][0], qh[ds][1], qh[ds][2], qh[ds][3], bh0, bh1);
                    mma_bf16(s0[0], s0[1], s0[2], s0[3],
                             ql[ds][0], ql[ds][1], ql[ds][2], ql[ds][3], bh0, bh1);
                    mma_bf16(s0[0], s0[1], s0[2], s0[3],
                             qh[ds][0], qh[ds][1], qh[ds][2], qh[ds][3], bl0, bl1);
                    mma_bf16(s1[0], s1[1], s1[2], s1[3],
                             qh[ds][0], qh[ds][1], qh[ds][2], qh[ds][3], bh2, bh3);
                    mma_bf16(s1[0], s1[1], s1[2], s1[3],
                             ql[ds][0], ql[ds][1], ql[ds][2], ql[ds][3], bh2, bh3);
                    mma_bf16(s1[0], s1[1], s1[2], s1[3],
                             qh[ds][0], qh[ds][1], qh[ds][2], qh[ds][3], bl2, bl3);
                }
            }
        }

        if (kt >= 2 * qblk) {
            const int row0 = qblk * 128 + 16 * w + g;
            #pragma unroll
            for (int nf = 0; nf < 8; nf++) {
                const int col = kt * 64 + 8 * nf + 2 * q;
                if (col     > row0)     s[nf][0] = -CUDART_INF_F;
                if (col + 1 > row0)     s[nf][1] = -CUDART_INF_F;
                if (col     > row0 + 8) s[nf][2] = -CUDART_INF_F;
                if (col + 1 > row0 + 8) s[nf][3] = -CUDART_INF_F;
            }
        }

        float tm0 = -CUDART_INF_F, tm1 = -CUDART_INF_F;
        #pragma unroll
        for (int nf = 0; nf < 8; nf++) {
            tm0 = fmaxf(tm0, fmaxf(s[nf][0], s[nf][1]));
            tm1 = fmaxf(tm1, fmaxf(s[nf][2], s[nf][3]));
        }
        tm0 = fmaxf(tm0, __shfl_xor_sync(0xffffffffu, tm0, 1));
        tm0 = fmaxf(tm0, __shfl_xor_sync(0xffffffffu, tm0, 2));
        tm1 = fmaxf(tm1, __shfl_xor_sync(0xffffffffu, tm1, 1));
        tm1 = fmaxf(tm1, __shfl_xor_sync(0xffffffffu, tm1, 2));

        const float m0n = fmaxf(m0, tm0);
        const float m1n = fmaxf(m1, tm1);
        const float cr0 = exp2f((m0 - m0n) * ATT_C);
        const float cr1 = exp2f((m1 - m1n) * ATT_C);
        m0 = m0n; m1 = m1n;
        l0 *= cr0; l1 *= cr1;
        #pragma unroll
        for (int nf = 0; nf < 16; nf++) {
            o[nf][0] *= cr0; o[nf][1] *= cr0;
            o[nf][2] *= cr1; o[nf][3] *= cr1;
        }

        unsigned ph[8][2], pl[8][2];
        #pragma unroll
        for (int nf = 0; nf < 8; nf++) {
            float p0 = exp2f((s[nf][0] - m0) * ATT_C);
            float p1 = exp2f((s[nf][1] - m0) * ATT_C);
            float p2 = exp2f((s[nf][2] - m1) * ATT_C);
            float p3 = exp2f((s[nf][3] - m1) * ATT_C);
            l0 += p0 + p1;
            l1 += p2 + p3;
            __nv_bfloat162 h01 = __floats2bfloat162_rn(p0, p1);
            __nv_bfloat162 h23 = __floats2bfloat162_rn(p2, p3);
            __nv_bfloat162 e01 = __floats2bfloat162_rn(p0 - __low2float(h01),
                                                       p1 - __high2float(h01));
            __nv_bfloat162 e23 = __floats2bfloat162_rn(p2 - __low2float(h23),
                                                       p3 - __high2float(h23));
            ph[nf][0] = bf2u(h01); ph[nf][1] = bf2u(h23);
            pl[nf][0] = bf2u(e01); pl[nf][1] = bf2u(e23);
        }

        {
            const int vrow   = (lane & 15);
            const int vchunk = 8 * (lane >> 4);
            #pragma unroll
            for (int j = 0; j < 4; j++) {
                const unsigned ah0 = ph[2 * j][0],     ah1 = ph[2 * j][1];
                const unsigned ah2 = ph[2 * j + 1][0], ah3 = ph[2 * j + 1][1];
                const unsigned al0 = pl[2 * j][0],     al1 = pl[2 * j][1];
                const unsigned al2 = pl[2 * j + 1][0], al3 = pl[2 * j + 1][1];
                #pragma unroll
                for (int nfp = 0; nfp < 8; nfp++) {
                    unsigned a = sbase + 2 * (VH_OFF + (16 * j + vrow) * RSTR
                                              + 16 * nfp + vchunk);
                    unsigned vh0, vh1, vh2, vh3, vl0, vl1, vl2, vl3;
                    ldsm_x4t(vh0, vh1, vh2, vh3, a);
                    ldsm_x4t(vl0, vl1, vl2, vl3, a + 2 * (VL_OFF - VH_OFF));
                    float* o0 = o[2 * nfp];
                    float* o1 = o[2 * nfp + 1];
                    mma_bf16(o0[0], o0[1], o0[2], o0[3], ah0, ah1, ah2, ah3, vh0, vh1);
                    mma_bf16(o0[0], o0[1], o0[2], o0[3], al0, al1, al2, al3, vh0, vh1);
                    mma_bf16(o0[0], o0[1], o0[2], o0[3], ah0, ah1, ah2, ah3, vl0, vl1);
                    mma_bf16(o1[0], o1[1], o1[2], o1[3], ah0, ah1, ah2, ah3, vh2, vh3);
                    mma_bf16(o1[0], o1[1], o1[2], o1[3], al0, al1, al2, al3, vh2, vh3);
                    mma_bf16(o1[0], o1[1], o1[2], o1[3], ah0, ah1, ah2, ah3, vl2, vl3);
                }
            }
        }
    }

    l0 += __shfl_xor_sync(0xffffffffu, l0, 1);
    l0 += __shfl_xor_sync(0xffffffffu, l0, 2);
    l1 += __shfl_xor_sync(0xffffffffu, l1, 1);
    l1 += __shfl_xor_sync(0xffffffffu, l1, 2);
    const float inv0 = 1.f / l0;
    const float inv1 = 1.f / l1;

    const size_t row0 = (size_t)(b * SEQ + qblk * 128 + 16 * w + g);
    unsigned* obh = (unsigned*)(outh + row0 * DMODEL + h * DHEAD);
    unsigned* obl = (unsigned*)(outl + row0 * DMODEL + h * DHEAD);
    #pragma unroll
    for (int nf = 0; nf < 16; nf++) {
        const int ci = 4 * nf + q;
        float x0 = o[nf][0] * inv0, x1 = o[nf][1] * inv0;
        float y0 = o[nf][2] * inv1, y1 = o[nf][3] * inv1;
        __nv_bfloat162 xh = __floats2bfloat162_rn(x0, x1);
        __nv_bfloat162 yh = __floats2bfloat162_rn(y0, y1);
        __nv_bfloat162 xl = __floats2bfloat162_rn(x0 - __low2float(xh),
                                                  x1 - __high2float(xh));
        __nv_bfloat162 yl = __floats2bfloat162_rn(y0 - __low2float(yh),
                                                  y1 - __high2float(yh));
        obh[ci] = bf2u(xh);
        obl[ci] = bf2u(xl);
        obh[ci + 4 * DMODEL] = bf2u(yh);
        obl[ci + 4 * DMODEL] = bf2u(yl);
    }
}

// ---------------------------------------------------------------------------
// kernel_launch
// ---------------------------------------------------------------------------
extern "C" void kernel_launch(void* const* d_in, const int* in_sizes, int n_in,
                              void* d_out, int out_size)
{
    const float* x     = (const float*)d_in[0];
    const float* W_qkv = (const float*)d_in[1];
    const float* b_qkv = (const float*)d_in[2];
    const float* W_out = (const float*)d_in[3];
    const float* b_out = (const float*)d_in[4];
    float* out = (float*)d_out;

    __nv_bfloat16 *qh, *ql, *xh, *xl, *wqh, *wql, *woh, *wol, *ath, *atl;
    cudaGetSymbolAddress((void**)&qh,  g_qkvh);
    cudaGetSymbolAddress((void**)&ql,  g_qkvl);
    cudaGetSymbolAddress((void**)&xh,  g_xh);
    cudaGetSymbolAddress((void**)&xl,  g_xl);
    cudaGetSymbolAddress((void**)&wqh, g_wqkvth);
    cudaGetSymbolAddress((void**)&wql, g_wqkvtl);
    cudaGetSymbolAddress((void**)&woh, g_woutth);
    cudaGetSymbolAddress((void**)&wol, g_wouttl);
    cudaGetSymbolAddress((void**)&ath, g_attnh);
    cudaGetSymbolAddress((void**)&atl, g_attnl);

    cudaFuncSetAttribute(flash_attn_tc_kernel,
                         cudaFuncAttributeMaxDynamicSharedMemorySize,
                         ATT_SMEM_BYTES);
    cudaFuncSetAttribute(gemm_planes_bias_kernel,
                         cudaFuncAttributeMaxDynamicSharedMemorySize,
                         GEMM_SMEM_BYTES);

    // Prep
    split_rm_kernel<<<(MTOT * DMODEL / 4 + 255) / 256, 256>>>(
        (const float4*)x, (uint2*)xh, (uint2*)xl, MTOT * DMODEL / 4);
    split_tr_kernel<<<dim3(DM3 / 32, DMODEL / 32), 256>>>(
        W_qkv, wqh, wql, DMODEL, DM3);
    split_tr_kernel<<<dim3(DMODEL / 32, DMODEL / 32), 256>>>(
        W_out, woh, wol, DMODEL, DMODEL);

    // 1) QKV GEMM -> bf16 hi/lo planes
    gemm_planes_bias_kernel<<<dim3(DM3 / 128, MTOT / 128), 256, GEMM_SMEM_BYTES>>>(
        xh, xl, wqh, wql, b_qkv, nullptr, qh, ql, MTOT, DM3, DMODEL);

    // 2) Flash attention (plane inputs) -> bf16 hi/lo planes
    flash_attn_tc_kernel<<<dim3(16, NHEADS, BATCH), 256, ATT_SMEM_BYTES>>>(
        qh, ql, ath, atl);

    // 3) Output GEMM -> fp32
    gemm_planes_bias_kernel<<<dim3(DMODEL / 128, MTOT / 128), 256, GEMM_SMEM_BYTES>>>(
        ath, atl, woh, wol, b_out, out, nullptr, nullptr, MTOT, DMODEL, DMODEL);
}

// round 12
// speedup vs baseline: 1.4005x; 1.2855x over previous
#include <cuda_runtime.h>
#include <cuda_bf16.h>
#include <math_constants.h>

#define BATCH   2
#define SEQ     2048
#define NHEADS  16
#define DHEAD   128
#define DMODEL  2048
#define DM3     6144
#define MTOT    4096

// Scratch (device globals)
__device__ __nv_bfloat16 g_qkvh[(size_t)MTOT * DM3];
__device__ __nv_bfloat16 g_qkvl[(size_t)MTOT * DM3];
__device__ __nv_bfloat16 g_xh[(size_t)MTOT * DMODEL];
__device__ __nv_bfloat16 g_xl[(size_t)MTOT * DMODEL];
__device__ __nv_bfloat16 g_wqkvth[(size_t)DM3 * DMODEL];   // [N=6144][K=2048]
__device__ __nv_bfloat16 g_wqkvtl[(size_t)DM3 * DMODEL];
__device__ __nv_bfloat16 g_woutth[(size_t)DMODEL * DMODEL];
__device__ __nv_bfloat16 g_wouttl[(size_t)DMODEL * DMODEL];
__device__ __nv_bfloat16 g_attnh[(size_t)MTOT * DMODEL];
__device__ __nv_bfloat16 g_attnl[(size_t)MTOT * DMODEL];

// ---------------------------------------------------------------------------
// Helpers
// ---------------------------------------------------------------------------
static __device__ __forceinline__ void mma_bf16(
    float& c0, float& c1, float& c2, float& c3,
    unsigned a0, unsigned a1, unsigned a2, unsigned a3,
    unsigned b0, unsigned b1)
{
    asm volatile(
        "mma.sync.aligned.m16n8k16.row.col.f32.bf16.bf16.f32 "
        "{%0,%1,%2,%3}, {%4,%5,%6,%7}, {%8,%9}, {%0,%1,%2,%3};\n"
        : "+f"(c0), "+f"(c1), "+f"(c2), "+f"(c3)
        : "r"(a0), "r"(a1), "r"(a2), "r"(a3), "r"(b0), "r"(b1));
}
static __device__ __forceinline__ void ldsm_x4(
    unsigned& r0, unsigned& r1, unsigned& r2, unsigned& r3, unsigned addr)
{
    asm volatile("ldmatrix.sync.aligned.m8n8.x4.shared.b16 {%0,%1,%2,%3}, [%4];\n"
                 : "=r"(r0), "=r"(r1), "=r"(r2), "=r"(r3) : "r"(addr));
}
static __device__ __forceinline__ void ldsm_x4t(
    unsigned& r0, unsigned& r1, unsigned& r2, unsigned& r3, unsigned addr)
{
    asm volatile("ldmatrix.sync.aligned.m8n8.x4.trans.shared.b16 {%0,%1,%2,%3}, [%4];\n"
                 : "=r"(r0), "=r"(r1), "=r"(r2), "=r"(r3) : "r"(addr));
}
static __device__ __forceinline__ unsigned bf2u(__nv_bfloat162 v) {
    return *reinterpret_cast<unsigned*>(&v);
}
static __device__ __forceinline__ void split4(float4 f, uint2& hi, uint2& lo) {
    __nv_bfloat162 h0 = __floats2bfloat162_rn(f.x, f.y);
    __nv_bfloat162 h1 = __floats2bfloat162_rn(f.z, f.w);
    float hx = __low2float(h0), hy = __high2float(h0);
    float hz = __low2float(h1), hw = __high2float(h1);
    __nv_bfloat162 l0 = __floats2bfloat162_rn(f.x - hx, f.y - hy);
    __nv_bfloat162 l1 = __floats2bfloat162_rn(f.z - hz, f.w - hw);
    hi.x = bf2u(h0); hi.y = bf2u(h1);
    lo.x = bf2u(l0); lo.y = bf2u(l1);
}
static __device__ __forceinline__ void cpa16(unsigned saddr, const void* g) {
    asm volatile("cp.async.cg.shared.global [%0], [%1], 16;\n"
                 :: "r"(saddr), "l"(g));
}
static __device__ __forceinline__ void cpa_commit() {
    asm volatile("cp.async.commit_group;\n" ::: "memory");
}

// ---------------------------------------------------------------------------
// Prep kernels: fp32 -> bf16 hi/lo planes
// ---------------------------------------------------------------------------
__global__ __launch_bounds__(256) void split_rm_kernel(
    const float4* __restrict__ src, uint2* __restrict__ h, uint2* __restrict__ l,
    int n4)
{
    int i = blockIdx.x * 256 + threadIdx.x;
    if (i < n4) {
        uint2 hi, lo;
        split4(src[i], hi, lo);
        h[i] = hi; l[i] = lo;
    }
}

// W [K][N] fp32 -> Wt hi/lo [N][K] bf16
__global__ __launch_bounds__(256) void split_tr_kernel(
    const float* __restrict__ W,
    __nv_bfloat16* __restrict__ th, __nv_bfloat16* __restrict__ tl,
    int K, int N)
{
    __shared__ float tile[32][33];
    const int n0 = blockIdx.x * 32, k0 = blockIdx.y * 32;
    const int tx = threadIdx.x & 31, ty = threadIdx.x >> 5;  // 32 x 8
    #pragma unroll
    for (int i = 0; i < 32; i += 8)
        tile[ty + i][tx] = W[(size_t)(k0 + ty + i) * N + (n0 + tx)];
    __syncthreads();
    #pragma unroll
    for (int i = 0; i < 32; i += 8) {
        float v = tile[tx][ty + i];
        __nv_bfloat16 hb = __float2bfloat16(v);
        __nv_bfloat16 lb = __float2bfloat16(v - __bfloat162float(hb));
        size_t o = (size_t)(n0 + ty + i) * K + (k0 + tx);
        th[o] = hb; tl[o] = lb;
    }
}

// ---------------------------------------------------------------------------
// Plane GEMM (round-5 measured-best mainloop): C = (Ah+Al) @ (Bh+Bl)^T + bias
// Block 128x128, ktile 32, 256 threads = 8 warps (4m x 2n), warp tile 32x64.
// Padded smem GST=40, 2-stage cp.async double buffer, wait_group 0.
// 80KB smem/CTA -> 2 CTAs/SM; launch_bounds(256,2) pins regs <= 128.
// Plane half-offsets within a buffer: Ah=0, Al=PLN, Bh=2*PLN, Bl=3*PLN.
// Output: fp32 C (Cf != nullptr) or bf16 hi/lo planes (Ch, Cl).
// ---------------------------------------------------------------------------
#define GST 40                       // halves per smem row (32 + 8 pad)
#define PLN (128 * GST)              // plane size in halves (5120)
#define BUFH (4 * PLN)               // buffer stride in halves (20480)
#define GEMM_SMEM_BYTES (2 * BUFH * 2)   // 81920

__global__ __launch_bounds__(256, 2) void gemm_planes_bias_kernel(
    const __nv_bfloat16* __restrict__ Ah, const __nv_bfloat16* __restrict__ Al,
    const __nv_bfloat16* __restrict__ Bh, const __nv_bfloat16* __restrict__ Bl,
    const float* __restrict__ bias,
    float* __restrict__ Cf,
    __nv_bfloat16* __restrict__ Ch, __nv_bfloat16* __restrict__ Cl,
    int M, int N, int K)
{
    extern __shared__ __nv_bfloat16 sm[];
    const unsigned sb = (unsigned)__cvta_generic_to_shared(sm);

    const int t = threadIdx.x, lane = t & 31, wid = t >> 5;
    const int bm = blockIdx.y, bn = blockIdx.x;
    const int warp_m = wid >> 1, warp_n = wid & 1;

    const int lr = t >> 1;
    const int ls = (t & 1) * 16;
    const __nv_bfloat16* Ahg = Ah + (size_t)(bm * 128 + lr) * K + ls;
    const __nv_bfloat16* Alg = Al + (size_t)(bm * 128 + lr) * K + ls;
    const __nv_bfloat16* Bhg = Bh + (size_t)(bn * 128 + lr) * K + ls;
    const __nv_bfloat16* Blg = Bl + (size_t)(bn * 128 + lr) * K + ls;
    const unsigned sAd = sb + 2 * (lr * GST + ls);

    float c[2][8][4];
    #pragma unroll
    for (int mf = 0; mf < 2; mf++)
        #pragma unroll
        for (int nf = 0; nf < 8; nf++)
            #pragma unroll
            for (int i = 0; i < 4; i++) c[mf][nf][i] = 0.f;

    const int nK = K / 32;

    // Prologue: tile 0 into buf 0  (byte offsets: Ah 0, Al 2*PLN, Bh 4*PLN, Bl 6*PLN)
    {
        unsigned d = sAd;
        cpa16(d,                 Ahg);
        cpa16(d + 16,            Ahg + 8);
        cpa16(d + 2 * PLN,       Alg);
        cpa16(d + 2 * PLN + 16,  Alg + 8);
        cpa16(d + 4 * PLN,       Bhg);
        cpa16(d + 4 * PLN + 16,  Bhg + 8);
        cpa16(d + 6 * PLN,       Blg);
        cpa16(d + 6 * PLN + 16,  Blg + 8);
        cpa_commit();
    }

    int buf = 0;
    for (int kt = 0; kt < nK; kt++) {
        asm volatile("cp.async.wait_group 0;\n" ::: "memory");
        __syncthreads();

        if (kt + 1 < nK) {
            const int go = (kt + 1) * 32;
            unsigned d = sAd + 2 * (buf ^ 1) * BUFH;
            cpa16(d,                 Ahg + go);
            cpa16(d + 16,            Ahg + go + 8);
            cpa16(d + 2 * PLN,       Alg + go);
            cpa16(d + 2 * PLN + 16,  Alg + go + 8);
            cpa16(d + 4 * PLN,       Bhg + go);
            cpa16(d + 4 * PLN + 16,  Bhg + go + 8);
            cpa16(d + 6 * PLN,       Blg + go);
            cpa16(d + 6 * PLN + 16,  Blg + go + 8);
            cpa_commit();
        }

        const unsigned base = sb + 2 * buf * BUFH;
        #pragma unroll
        for (int s = 0; s < 2; s++) {
            unsigned ah[2][4], al[2][4];
            #pragma unroll
            for (int mf = 0; mf < 2; mf++) {
                const int row = warp_m * 32 + mf * 16 + (lane & 15);
                const unsigned a = base + 2 * (row * GST + 16 * s + 8 * (lane >> 4));
                ldsm_x4(ah[mf][0], ah[mf][1], ah[mf][2], ah[mf][3], a);
                ldsm_x4(al[mf][0], al[mf][1], al[mf][2], al[mf][3], a + 2 * PLN);
            }
            #pragma unroll
            for (int nfp = 0; nfp < 4; nfp++) {
                const int nrow = warp_n * 64 + nfp * 16 + (lane & 7) + 8 * (lane >> 4);
                // Bh plane at half offset 2*PLN -> inside 2*(...) ; Bl = +2*PLN bytes
                const unsigned a = base + 2 * (2 * PLN + nrow * GST
                                               + 16 * s + 8 * ((lane >> 3) & 1));
                unsigned bh0, bh1, bh2, bh3, bl0, bl1, bl2, bl3;
                ldsm_x4(bh0, bh1, bh2, bh3, a);
                ldsm_x4(bl0, bl1, bl2, bl3, a + 2 * PLN);
                #pragma unroll
                for (int mf = 0; mf < 2; mf++) {
                    float* c0 = c[mf][2 * nfp];
                    float* c1 = c[mf][2 * nfp + 1];
                    mma_bf16(c0[0], c0[1], c0[2], c0[3],
                             ah[mf][0], ah[mf][1], ah[mf][2], ah[mf][3], bh0, bh1);
                    mma_bf16(c0[0], c0[1], c0[2], c0[3],
                             al[mf][0], al[mf][1], al[mf][2], al[mf][3], bh0, bh1);
                    mma_bf16(c0[0], c0[1], c0[2], c0[3],
                             ah[mf][0], ah[mf][1], ah[mf][2], ah[mf][3], bl0, bl1);
                    mma_bf16(c1[0], c1[1], c1[2], c1[3],
                             ah[mf][0], ah[mf][1], ah[mf][2], ah[mf][3], bh2, bh3);
                    mma_bf16(c1[0], c1[1], c1[2], c1[3],
                             al[mf][0], al[mf][1], al[mf][2], al[mf][3], bh2, bh3);
                    mma_bf16(c1[0], c1[1], c1[2], c1[3],
                             ah[mf][0], ah[mf][1], ah[mf][2], ah[mf][3], bl2, bl3);
                }
            }
        }
        buf ^= 1;
    }

    // Epilogue
    const int g = lane >> 2, q = lane & 3;
    const int crow0 = bm * 128 + warp_m * 32 + g;
    const int ccol0 = bn * 128 + warp_n * 64 + 2 * q;
    if (Cf) {
        #pragma unroll
        for (int nf = 0; nf < 8; nf++) {
            const int col = ccol0 + nf * 8;
            const float bx = bias[col];
            const float by = bias[col + 1];
            #pragma unroll
            for (int mf = 0; mf < 2; mf++) {
                const int row = crow0 + mf * 16;
                *(float2*)(Cf + (size_t)row * N + col) =
                    make_float2(c[mf][nf][0] + bx, c[mf][nf][1] + by);
                *(float2*)(Cf + (size_t)(row + 8) * N + col) =
                    make_float2(c[mf][nf][2] + bx, c[mf][nf][3] + by);
            }
        }
    } else {
        unsigned* Chu = (unsigned*)Ch;
        unsigned* Clu = (unsigned*)Cl;
        const int nh = N / 2;
        #pragma unroll
        for (int nf = 0; nf < 8; nf++) {
            const int col = ccol0 + nf * 8;
            const float bx = bias[col];
            const float by = bias[col + 1];
            #pragma unroll
            for (int mf = 0; mf < 2; mf++) {
                const int row = crow0 + mf * 16;
                float v0 = c[mf][nf][0] + bx, v1 = c[mf][nf][1] + by;
                float w0 = c[mf][nf][2] + bx, w1 = c[mf][nf][3] + by;
                __nv_bfloat162 vh = __floats2bfloat162_rn(v0, v1);
                __nv_bfloat162 wh = __floats2bfloat162_rn(w0, w1);
                __nv_bfloat162 vl = __floats2bfloat162_rn(v0 - __low2float(vh),
                                                          v1 - __high2float(vh));
                __nv_bfloat162 wl = __floats2bfloat162_rn(w0 - __low2float(wh),
                                                          w1 - __high2float(wh));
                Chu[(size_t)row * nh + col / 2]       = bf2u(vh);
                Clu[(size_t)row * nh + col / 2]       = bf2u(vl);
                Chu[(size_t)(row + 8) * nh + col / 2] = bf2u(wh);
                Clu[(size_t)(row + 8) * nh + col / 2] = bf2u(wl);
            }
        }
    }
}

// ---------------------------------------------------------------------------
// Tensor-core flash attention (causal), triple-bf16, 2-stage cp.async KV ring.
// Smem: 2 stages x 34816 halves. Stage = KH|KL|VH|VL, each 64 rows x 136 halves.
// Q planes staged in stage 0 only for fragment extraction, then overwritten.
// ---------------------------------------------------------------------------
#define ATT_C 0.12751666769323707f  // (1/sqrt(128)) * log2(e)
#define RSTR  136
#define KVPLN (64 * RSTR)            // 8704 halves per plane
#define KVSTG (4 * KVPLN)            // 34816 halves per stage
#define ATT_SMEM_BYTES (2 * KVSTG * 2)   // 139264

__global__ __launch_bounds__(256) void flash_attn_tc_kernel(
    const __nv_bfloat16* __restrict__ qkvh, const __nv_bfloat16* __restrict__ qkvl,
    __nv_bfloat16* __restrict__ outh, __nv_bfloat16* __restrict__ outl)
{
    extern __shared__ unsigned smu[];
    const unsigned sbase = (unsigned)__cvta_generic_to_shared(smu);

    const int qblk = blockIdx.x;
    const int h    = blockIdx.y;
    const int b    = blockIdx.z;
    const int tid  = threadIdx.x;
    const int lane = tid & 31;
    const int w    = tid >> 5;
    const int g    = lane >> 2;
    const int q    = lane & 3;

    // ---- Load Q planes into stage-0 region: QH at half 0, QL at half 17408
    {
        const int r  = tid >> 1;
        const int c0 = (tid & 1) * 64;
        const size_t gofs = (size_t)(b * SEQ + qblk * 128 + r) * DM3 + h * DHEAD + c0;
        const uint4* qhp = (const uint4*)(qkvh + gofs);
        const uint4* qlp = (const uint4*)(qkvl + gofs);
        #pragma unroll
        for (int i = 0; i < 8; i++) {
            const int hofs = r * RSTR + c0 + 8 * i;
            *(uint4*)(smu + hofs / 2) = qhp[i];
            *(uint4*)(smu + (17408 + hofs) / 2) = qlp[i];
        }
    }
    __syncthreads();

    // ---- Extract Q fragments to registers
    unsigned qh[8][4], ql[8][4];
    {
        const int row = 16 * w + (lane & 15);
        const int cb  = 8 * (lane >> 4);
        #pragma unroll
        for (int ds = 0; ds < 8; ds++) {
            unsigned a = sbase + 2 * (row * RSTR + 16 * ds + cb);
            ldsm_x4(qh[ds][0], qh[ds][1], qh[ds][2], qh[ds][3], a);
            ldsm_x4(ql[ds][0], ql[ds][1], ql[ds][2], ql[ds][3], a + 2 * 17408);
        }
    }
    __syncthreads();   // all warps done with Q smem; stages may be overwritten

    const int ntiles = 2 * qblk + 2;

    // KV loader: 16 cpa16/thread, 16 consecutive lanes cover one 256B row.
    const int kv_r0 = tid >> 4;          // base row 0..15
    const int kv_ch = (tid & 15) * 8;    // chunk offset in halves
    auto issue_kv = [&](int kt, int stage) {
        const unsigned sb0 = sbase + 2 * stage * KVSTG;
        #pragma unroll
        for (int p = 0; p < 4; p++) {
            const __nv_bfloat16* plane_base =
                ((p & 1) ? qkvl : qkvh) + DMODEL + ((p >> 1) ? DMODEL : 0)
                + h * DHEAD + kv_ch;
            #pragma unroll
            for (int j = 0; j < 4; j++) {
                const int row = kv_r0 + 16 * j;
                cpa16(sb0 + 2 * (p * KVPLN + row * RSTR + kv_ch),
                      plane_base + (size_t)(b * SEQ + kt * 64 + row) * DM3);
            }
        }
        cpa_commit();
    };

    issue_kv(0, 0);
    issue_kv(1, 1);

    float o[16][4];
    #pragma unroll
    for (int nf = 0; nf < 16; nf++)
        #pragma unroll
        for (int i = 0; i < 4; i++) o[nf][i] = 0.f;
    float m0 = -1e30f, m1 = -1e30f, l0 = 0.f, l1 = 0.f;

    const int warp_row_max = qblk * 128 + 16 * w + 15;

    for (int kt = 0; kt < ntiles; kt++) {
        asm volatile("cp.async.wait_group 1;\n" ::: "memory");
        __syncthreads();

        const unsigned stg = sbase + 2 * (kt & 1) * KVSTG;

        if (kt * 64 <= warp_row_max) {
            float s[8][4];
            #pragma unroll
            for (int nf = 0; nf < 8; nf++)
                #pragma unroll
                for (int i = 0; i < 4; i++) s[nf][i] = 0.f;

            {
                const int krow   = (lane & 7) + 8 * (lane >> 4);
                const int kchunk = 8 * ((lane >> 3) & 1);
                #pragma unroll
                for (int ds = 0; ds < 8; ds++) {
                    #pragma unroll
                    for (int nfp = 0; nfp < 4; nfp++) {
                        unsigned a = stg + 2 * ((16 * nfp + krow) * RSTR
                                                + 16 * ds + kchunk);
                        unsigned bh0, bh1, bh2, bh3, bl0, bl1, bl2, bl3;
                        ldsm_x4(bh0, bh1, bh2, bh3, a);
                        ldsm_x4(bl0, bl1, bl2, bl3, a + 2 * KVPLN);
                        float* s0 = s[2 * nfp];
                        float* s1 = s[2 * nfp + 1];
                        mma_bf16(s0[0], s0[1], s0[2], s0[3],
                                 qh[ds][0], qh[ds][1], qh[ds][2], qh[ds][3], bh0, bh1);
                        mma_bf16(s0[0], s0[1], s0[2], s0[3],
                                 ql[ds][0], ql[ds][1], ql[ds][2], ql[ds][3], bh0, bh1);
                        mma_bf16(s0[0], s0[1], s0[2], s0[3],
                                 qh[ds][0], qh[ds][1], qh[ds][2], qh[ds][3], bl0, bl1);
                        mma_bf16(s1[0], s1[1], s1[2], s1[3],
                                 qh[ds][0], qh[ds][1], qh[ds][2], qh[ds][3], bh2, bh3);
                        mma_bf16(s1[0], s1[1], s1[2], s1[3],
                                 ql[ds][0], ql[ds][1], ql[ds][2], ql[ds][3], bh2, bh3);
                        mma_bf16(s1[0], s1[1], s1[2], s1[3],
                                 qh[ds][0], qh[ds][1], qh[ds][2], qh[ds][3], bl2, bl3);
                    }
                }
            }

            if (kt >= 2 * qblk) {
                const int row0 = qblk * 128 + 16 * w + g;
                #pragma unroll
                for (int nf = 0; nf < 8; nf++) {
                    const int col = kt * 64 + 8 * nf + 2 * q;
                    if (col     > row0)     s[nf][0] = -CUDART_INF_F;
                    if (col + 1 > row0)     s[nf][1] = -CUDART_INF_F;
                    if (col     > row0 + 8) s[nf][2] = -CUDART_INF_F;
                    if (col + 1 > row0 + 8) s[nf][3] = -CUDART_INF_F;
                }
            }

            float tm0 = -CUDART_INF_F, tm1 = -CUDART_INF_F;
            #pragma unroll
            for (int nf = 0; nf < 8; nf++) {
                tm0 = fmaxf(tm0, fmaxf(s[nf][0], s[nf][1]));
                tm1 = fmaxf(tm1, fmaxf(s[nf][2], s[nf][3]));
            }
            tm0 = fmaxf(tm0, __shfl_xor_sync(0xffffffffu, tm0, 1));
            tm0 = fmaxf(tm0, __shfl_xor_sync(0xffffffffu, tm0, 2));
            tm1 = fmaxf(tm1, __shfl_xor_sync(0xffffffffu, tm1, 1));
            tm1 = fmaxf(tm1, __shfl_xor_sync(0xffffffffu, tm1, 2));

            const float m0n = fmaxf(m0, tm0);
            const float m1n = fmaxf(m1, tm1);
            const float cr0 = exp2f((m0 - m0n) * ATT_C);
            const float cr1 = exp2f((m1 - m1n) * ATT_C);
            m0 = m0n; m1 = m1n;
            l0 *= cr0; l1 *= cr1;
            #pragma unroll
            for (int nf = 0; nf < 16; nf++) {
                o[nf][0] *= cr0; o[nf][1] *= cr0;
                o[nf][2] *= cr1; o[nf][3] *= cr1;
            }

            unsigned ph[8][2], pl[8][2];
            #pragma unroll
            for (int nf = 0; nf < 8; nf++) {
                float p0 = exp2f((s[nf][0] - m0) * ATT_C);
                float p1 = exp2f((s[nf][1] - m0) * ATT_C);
                float p2 = exp2f((s[nf][2] - m1) * ATT_C);
                float p3 = exp2f((s[nf][3] - m1) * ATT_C);
                l0 += p0 + p1;
                l1 += p2 + p3;
                __nv_bfloat162 h01 = __floats2bfloat162_rn(p0, p1);
                __nv_bfloat162 h23 = __floats2bfloat162_rn(p2, p3);
                __nv_bfloat162 e01 = __floats2bfloat162_rn(p0 - __low2float(h01),
                                                           p1 - __high2float(h01));
                __nv_bfloat162 e23 = __floats2bfloat162_rn(p2 - __low2float(h23),
                                                           p3 - __high2float(h23));
                ph[nf][0] = bf2u(h01); ph[nf][1] = bf2u(h23);
                pl[nf][0] = bf2u(e01); pl[nf][1] = bf2u(e23);
            }

            {
                const int vrow   = (lane & 15);
                const int vchunk = 8 * (lane >> 4);
                #pragma unroll
                for (int j = 0; j < 4; j++) {
                    const unsigned ah0 = ph[2 * j][0],     ah1 = ph[2 * j][1];
                    const unsigned ah2 = ph[2 * j + 1][0], ah3 = ph[2 * j + 1][1];
                    const unsigned al0 = pl[2 * j][0],     al1 = pl[2 * j][1];
                    const unsigned al2 = pl[2 * j + 1][0], al3 = pl[2 * j + 1][1];
                    #pragma unroll
                    for (int nfp = 0; nfp < 8; nfp++) {
                        unsigned a = stg + 2 * (2 * KVPLN + (16 * j + vrow) * RSTR
                                                + 16 * nfp + vchunk);
                        unsigned vh0, vh1, vh2, vh3, vl0, vl1, vl2, vl3;
                        ldsm_x4t(vh0, vh1, vh2, vh3, a);
                        ldsm_x4t(vl0, vl1, vl2, vl3, a + 2 * KVPLN);
                        float* o0 = o[2 * nfp];
                        float* o1 = o[2 * nfp + 1];
                        mma_bf16(o0[0], o0[1], o0[2], o0[3], ah0, ah1, ah2, ah3, vh0, vh1);
                        mma_bf16(o0[0], o0[1], o0[2], o0[3], al0, al1, al2, al3, vh0, vh1);
                        mma_bf16(o0[0], o0[1], o0[2], o0[3], ah0, ah1, ah2, ah3, vl0, vl1);
                        mma_bf16(o1[0], o1[1], o1[2], o1[3], ah0, ah1, ah2, ah3, vh2, vh3);
                        mma_bf16(o1[0], o1[1], o1[2], o1[3], al0, al1, al2, al3, vh2, vh3);
                        mma_bf16(o1[0], o1[1], o1[2], o1[3], ah0, ah1, ah2, ah3, vl2, vl3);
                    }
                }
            }
        }

        __syncthreads();   // all warps done reading stage kt&1
        if (kt + 2 < ntiles) issue_kv(kt + 2, kt & 1);
        else                 cpa_commit();   // keep group count uniform
    }

    l0 += __shfl_xor_sync(0xffffffffu, l0, 1);
    l0 += __shfl_xor_sync(0xffffffffu, l0, 2);
    l1 += __shfl_xor_sync(0xffffffffu, l1, 1);
    l1 += __shfl_xor_sync(0xffffffffu, l1, 2);
    const float inv0 = 1.f / l0;
    const float inv1 = 1.f / l1;

    const size_t row0 = (size_t)(b * SEQ + qblk * 128 + 16 * w + g);
    unsigned* obh = (unsigned*)(outh + row0 * DMODEL + h * DHEAD);
    unsigned* obl = (unsigned*)(outl + row0 * DMODEL + h * DHEAD);
    #pragma unroll
    for (int nf = 0; nf < 16; nf++) {
        const int ci = 4 * nf + q;
        float x0 = o[nf][0] * inv0, x1 = o[nf][1] * inv0;
        float y0 = o[nf][2] * inv1, y1 = o[nf][3] * inv1;
        __nv_bfloat162 xh = __floats2bfloat162_rn(x0, x1);
        __nv_bfloat162 yh = __floats2bfloat162_rn(y0, y1);
        __nv_bfloat162 xl = __floats2bfloat162_rn(x0 - __low2float(xh),
                                                  x1 - __high2float(xh));
        __nv_bfloat162 yl = __floats2bfloat162_rn(y0 - __low2float(yh),
                                                  y1 - __high2float(yh));
        obh[ci] = bf2u(xh);
        obl[ci] = bf2u(xl);
        obh[ci + 4 * DMODEL] = bf2u(yh);
        obl[ci + 4 * DMODEL] = bf2u(yl);
    }
}

// ---------------------------------------------------------------------------
// kernel_launch
// ---------------------------------------------------------------------------
extern "C" void kernel_launch(void* const* d_in, const int* in_sizes, int n_in,
                              void* d_out, int out_size)
{
    const float* x     = (const float*)d_in[0];
    const float* W_qkv = (const float*)d_in[1];
    const float* b_qkv = (const float*)d_in[2];
    const float* W_out = (const float*)d_in[3];
    const float* b_out = (const float*)d_in[4];
    float* out = (float*)d_out;

    __nv_bfloat16 *qh, *ql, *xh, *xl, *wqh, *wql, *woh, *wol, *ath, *atl;
    cudaGetSymbolAddress((void**)&qh,  g_qkvh);
    cudaGetSymbolAddress((void**)&ql,  g_qkvl);
    cudaGetSymbolAddress((void**)&xh,  g_xh);
    cudaGetSymbolAddress((void**)&xl,  g_xl);
    cudaGetSymbolAddress((void**)&wqh, g_wqkvth);
    cudaGetSymbolAddress((void**)&wql, g_wqkvtl);
    cudaGetSymbolAddress((void**)&woh, g_woutth);
    cudaGetSymbolAddress((void**)&wol, g_wouttl);
    cudaGetSymbolAddress((void**)&ath, g_attnh);
    cudaGetSymbolAddress((void**)&atl, g_attnl);

    cudaFuncSetAttribute(flash_attn_tc_kernel,
                         cudaFuncAttributeMaxDynamicSharedMemorySize,
                         ATT_SMEM_BYTES);
    cudaFuncSetAttribute(gemm_planes_bias_kernel,
                         cudaFuncAttributeMaxDynamicSharedMemorySize,
                         GEMM_SMEM_BYTES);

    // Prep
    split_rm_kernel<<<(MTOT * DMODEL / 4 + 255) / 256, 256>>>(
        (const float4*)x, (uint2*)xh, (uint2*)xl, MTOT * DMODEL / 4);
    split_tr_kernel<<<dim3(DM3 / 32, DMODEL / 32), 256>>>(
        W_qkv, wqh, wql, DMODEL, DM3);
    split_tr_kernel<<<dim3(DMODEL / 32, DMODEL / 32), 256>>>(
        W_out, woh, wol, DMODEL, DMODEL);

    // 1) QKV GEMM -> bf16 hi/lo planes
    gemm_planes_bias_kernel<<<dim3(DM3 / 128, MTOT / 128), 256, GEMM_SMEM_BYTES>>>(
        xh, xl, wqh, wql, b_qkv, nullptr, qh, ql, MTOT, DM3, DMODEL);

    // 2) Flash attention (plane inputs, pipelined KV) -> bf16 hi/lo planes
    flash_attn_tc_kernel<<<dim3(16, NHEADS, BATCH), 256, ATT_SMEM_BYTES>>>(
        qh, ql, ath, atl);

    // 3) Output GEMM -> fp32
    gemm_planes_bias_kernel<<<dim3(DMODEL / 128, MTOT / 128), 256, GEMM_SMEM_BYTES>>>(
        ath, atl, woh, wol, b_out, out, nullptr, nullptr, MTOT, DMODEL, DMODEL);
}

// round 13
// speedup vs baseline: 2.5562x; 1.8251x over previous
#include <cuda_runtime.h>
#include <cuda_bf16.h>
#include <cuda_fp16.h>
#include <math_constants.h>

#define BATCH   2
#define SEQ     2048
#define NHEADS  16
#define DHEAD   128
#define DMODEL  2048
#define DM3     6144
#define MTOT    4096

// Scratch (device globals)
__device__ __nv_bfloat16 g_qkvh[(size_t)MTOT * DM3];      // bf16 hi plane (attention in)
__device__ __nv_bfloat16 g_qkvl[(size_t)MTOT * DM3];      // bf16 lo plane
__device__ __half        g_x16[(size_t)MTOT * DMODEL];    // fp16 activations
__device__ __half        g_wqkvt16[(size_t)DM3 * DMODEL]; // fp16 W_qkv^T [N][K]
__device__ __half        g_woutt16[(size_t)DMODEL * DMODEL];
__device__ __half        g_att16[(size_t)MTOT * DMODEL];  // fp16 attention out

// ---------------------------------------------------------------------------
// Helpers
// ---------------------------------------------------------------------------
static __device__ __forceinline__ void mma_bf16(
    float& c0, float& c1, float& c2, float& c3,
    unsigned a0, unsigned a1, unsigned a2, unsigned a3,
    unsigned b0, unsigned b1)
{
    asm volatile(
        "mma.sync.aligned.m16n8k16.row.col.f32.bf16.bf16.f32 "
        "{%0,%1,%2,%3}, {%4,%5,%6,%7}, {%8,%9}, {%0,%1,%2,%3};\n"
        : "+f"(c0), "+f"(c1), "+f"(c2), "+f"(c3)
        : "r"(a0), "r"(a1), "r"(a2), "r"(a3), "r"(b0), "r"(b1));
}
static __device__ __forceinline__ void mma_fp16(
    float& c0, float& c1, float& c2, float& c3,
    unsigned a0, unsigned a1, unsigned a2, unsigned a3,
    unsigned b0, unsigned b1)
{
    asm volatile(
        "mma.sync.aligned.m16n8k16.row.col.f32.f16.f16.f32 "
        "{%0,%1,%2,%3}, {%4,%5,%6,%7}, {%8,%9}, {%0,%1,%2,%3};\n"
        : "+f"(c0), "+f"(c1), "+f"(c2), "+f"(c3)
        : "r"(a0), "r"(a1), "r"(a2), "r"(a3), "r"(b0), "r"(b1));
}
static __device__ __forceinline__ void ldsm_x4(
    unsigned& r0, unsigned& r1, unsigned& r2, unsigned& r3, unsigned addr)
{
    asm volatile("ldmatrix.sync.aligned.m8n8.x4.shared.b16 {%0,%1,%2,%3}, [%4];\n"
                 : "=r"(r0), "=r"(r1), "=r"(r2), "=r"(r3) : "r"(addr));
}
static __device__ __forceinline__ void ldsm_x4t(
    unsigned& r0, unsigned& r1, unsigned& r2, unsigned& r3, unsigned addr)
{
    asm volatile("ldmatrix.sync.aligned.m8n8.x4.trans.shared.b16 {%0,%1,%2,%3}, [%4];\n"
                 : "=r"(r0), "=r"(r1), "=r"(r2), "=r"(r3) : "r"(addr));
}
static __device__ __forceinline__ unsigned bf2u(__nv_bfloat162 v) {
    return *reinterpret_cast<unsigned*>(&v);
}
static __device__ __forceinline__ unsigned h2u(__half2 v) {
    return *reinterpret_cast<unsigned*>(&v);
}
static __device__ __forceinline__ void cpa16(unsigned saddr, const void* g) {
    asm volatile("cp.async.cg.shared.global [%0], [%1], 16;\n"
                 :: "r"(saddr), "l"(g));
}
static __device__ __forceinline__ void cpa_commit() {
    asm volatile("cp.async.commit_group;\n" ::: "memory");
}

// ---------------------------------------------------------------------------
// Prep kernels: fp32 -> fp16 plane
// ---------------------------------------------------------------------------
__global__ __launch_bounds__(256) void cvt_rm_kernel(
    const float4* __restrict__ src, uint2* __restrict__ d, int n4)
{
    int i = blockIdx.x * 256 + threadIdx.x;
    if (i < n4) {
        float4 f = src[i];
        uint2 o;
        o.x = h2u(__floats2half2_rn(f.x, f.y));
        o.y = h2u(__floats2half2_rn(f.z, f.w));
        d[i] = o;
    }
}

// W [K][N] fp32 -> Wt fp16 [N][K]
__global__ __launch_bounds__(256) void cvt_tr_kernel(
    const float* __restrict__ W, __half* __restrict__ wt, int K, int N)
{
    __shared__ float tile[32][33];
    const int n0 = blockIdx.x * 32, k0 = blockIdx.y * 32;
    const int tx = threadIdx.x & 31, ty = threadIdx.x >> 5;  // 32 x 8
    #pragma unroll
    for (int i = 0; i < 32; i += 8)
        tile[ty + i][tx] = W[(size_t)(k0 + ty + i) * N + (n0 + tx)];
    __syncthreads();
    #pragma unroll
    for (int i = 0; i < 32; i += 8)
        wt[(size_t)(n0 + ty + i) * K + (k0 + tx)] = __float2half_rn(tile[tx][ty + i]);
}

// ---------------------------------------------------------------------------
// fp16 GEMM: C = A[M,K] @ B^T[N,K] + bias, single fp16 mma, fp32 accumulate.
// Block 128x128, ktile 32, 256 threads = 8 warps (4m x 2n), warp tile 32x64.
// Smem stage = A plane + B plane, row stride GST=40 halves (conflict-free).
// 4-stage cp.async ring (wait_group 2, 3-deep lookahead), 80KB -> 2 CTAs/SM.
// Output: fp32 C (Cf != nullptr) or bf16 hi/lo planes (Ch, Cl).
// ---------------------------------------------------------------------------
#define GST 40                       // halves per smem row (32 + 8 pad)
#define PLN (128 * GST)              // plane size in halves (5120)
#define STG_H (2 * PLN)              // stage size in halves (10240) = 20480 B
#define NSTG 4
#define GEMM_SMEM_BYTES (NSTG * STG_H * 2)   // 81920

__global__ __launch_bounds__(256, 2) void gemm_fp16_bias_kernel(
    const __half* __restrict__ A, const __half* __restrict__ B,
    const float* __restrict__ bias,
    float* __restrict__ Cf,
    __nv_bfloat16* __restrict__ Ch, __nv_bfloat16* __restrict__ Cl,
    int M, int N, int K)
{
    extern __shared__ __half sm[];
    const unsigned sb = (unsigned)__cvta_generic_to_shared(sm);

    const int t = threadIdx.x, lane = t & 31, wid = t >> 5;
    const int bm = blockIdx.y, bn = blockIdx.x;
    const int warp_m = wid >> 1, warp_n = wid & 1;

    const int lr = t >> 1;
    const int ls = (t & 1) * 16;
    const __half* Ag = A + (size_t)(bm * 128 + lr) * K + ls;
    const __half* Bg = B + (size_t)(bn * 128 + lr) * K + ls;
    const unsigned sAd = sb + 2 * (lr * GST + ls);

    float c[2][8][4];
    #pragma unroll
    for (int mf = 0; mf < 2; mf++)
        #pragma unroll
        for (int nf = 0; nf < 8; nf++)
            #pragma unroll
            for (int i = 0; i < 4; i++) c[mf][nf][i] = 0.f;

    const int nK = K / 32;

    auto issue_stage = [&](int kt) {
        const int go = kt * 32;
        const unsigned d = sAd + 2 * (kt & 3) * STG_H;
        cpa16(d,                 Ag + go);
        cpa16(d + 16,            Ag + go + 8);
        cpa16(d + 2 * PLN,       Bg + go);
        cpa16(d + 2 * PLN + 16,  Bg + go + 8);
        cpa_commit();
    };

    issue_stage(0);
    issue_stage(1);
    issue_stage(2);

    for (int kt = 0; kt < nK; kt++) {
        asm volatile("cp.async.wait_group 2;\n" ::: "memory");
        __syncthreads();

        if (kt + 3 < nK) issue_stage(kt + 3);

        const unsigned base = sb + 2 * (kt & 3) * STG_H;
        #pragma unroll
        for (int s = 0; s < 2; s++) {
            unsigned ah[2][4];
            #pragma unroll
            for (int mf = 0; mf < 2; mf++) {
                const int row = warp_m * 32 + mf * 16 + (lane & 15);
                const unsigned a = base + 2 * (row * GST + 16 * s + 8 * (lane >> 4));
                ldsm_x4(ah[mf][0], ah[mf][1], ah[mf][2], ah[mf][3], a);
            }
            #pragma unroll
            for (int nfp = 0; nfp < 4; nfp++) {
                const int nrow = warp_n * 64 + nfp * 16 + (lane & 7) + 8 * (lane >> 4);
                const unsigned a = base + 2 * (PLN + nrow * GST
                                               + 16 * s + 8 * ((lane >> 3) & 1));
                unsigned b0, b1, b2, b3;
                ldsm_x4(b0, b1, b2, b3, a);
                #pragma unroll
                for (int mf = 0; mf < 2; mf++) {
                    float* c0 = c[mf][2 * nfp];
                    float* c1 = c[mf][2 * nfp + 1];
                    mma_fp16(c0[0], c0[1], c0[2], c0[3],
                             ah[mf][0], ah[mf][1], ah[mf][2], ah[mf][3], b0, b1);
                    mma_fp16(c1[0], c1[1], c1[2], c1[3],
                             ah[mf][0], ah[mf][1], ah[mf][2], ah[mf][3], b2, b3);
                }
            }
        }
    }

    // Epilogue
    const int g = lane >> 2, q = lane & 3;
    const int crow0 = bm * 128 + warp_m * 32 + g;
    const int ccol0 = bn * 128 + warp_n * 64 + 2 * q;
    if (Cf) {
        #pragma unroll
        for (int nf = 0; nf < 8; nf++) {
            const int col = ccol0 + nf * 8;
            const float bx = bias[col];
            const float by = bias[col + 1];
            #pragma unroll
            for (int mf = 0; mf < 2; mf++) {
                const int row = crow0 + mf * 16;
                *(float2*)(Cf + (size_t)row * N + col) =
                    make_float2(c[mf][nf][0] + bx, c[mf][nf][1] + by);
                *(float2*)(Cf + (size_t)(row + 8) * N + col) =
                    make_float2(c[mf][nf][2] + bx, c[mf][nf][3] + by);
            }
        }
    } else {
        unsigned* Chu = (unsigned*)Ch;
        unsigned* Clu = (unsigned*)Cl;
        const int nh = N / 2;
        #pragma unroll
        for (int nf = 0; nf < 8; nf++) {
            const int col = ccol0 + nf * 8;
            const float bx = bias[col];
            const float by = bias[col + 1];
            #pragma unroll
            for (int mf = 0; mf < 2; mf++) {
                const int row = crow0 + mf * 16;
                float v0 = c[mf][nf][0] + bx, v1 = c[mf][nf][1] + by;
                float w0 = c[mf][nf][2] + bx, w1 = c[mf][nf][3] + by;
                __nv_bfloat162 vh = __floats2bfloat162_rn(v0, v1);
                __nv_bfloat162 wh = __floats2bfloat162_rn(w0, w1);
                __nv_bfloat162 vl = __floats2bfloat162_rn(v0 - __low2float(vh),
                                                          v1 - __high2float(vh));
                __nv_bfloat162 wl = __floats2bfloat162_rn(w0 - __low2float(wh),
                                                          w1 - __high2float(wh));
                Chu[(size_t)row * nh + col / 2]       = bf2u(vh);
                Clu[(size_t)row * nh + col / 2]       = bf2u(vl);
                Chu[(size_t)(row + 8) * nh + col / 2] = bf2u(wh);
                Clu[(size_t)(row + 8) * nh + col / 2] = bf2u(wl);
            }
        }
    }
}

// ---------------------------------------------------------------------------
// Tensor-core flash attention (causal), triple-bf16, 2-stage cp.async KV ring.
// Inputs: bf16 hi/lo planes. Output: ONE fp16 plane (for fp16 out-GEMM).
// ---------------------------------------------------------------------------
#define ATT_C 0.12751666769323707f  // (1/sqrt(128)) * log2(e)
#define RSTR  136
#define KVPLN (64 * RSTR)            // 8704 halves per plane
#define KVSTG (4 * KVPLN)            // 34816 halves per stage
#define ATT_SMEM_BYTES (2 * KVSTG * 2)   // 139264

__global__ __launch_bounds__(256) void flash_attn_tc_kernel(
    const __nv_bfloat16* __restrict__ qkvh, const __nv_bfloat16* __restrict__ qkvl,
    __half* __restrict__ att)
{
    extern __shared__ unsigned smu[];
    const unsigned sbase = (unsigned)__cvta_generic_to_shared(smu);

    const int qblk = blockIdx.x;
    const int h    = blockIdx.y;
    const int b    = blockIdx.z;
    const int tid  = threadIdx.x;
    const int lane = tid & 31;
    const int w    = tid >> 5;
    const int g    = lane >> 2;
    const int q    = lane & 3;

    // ---- Load Q planes into stage-0 region: QH at half 0, QL at half 17408
    {
        const int r  = tid >> 1;
        const int c0 = (tid & 1) * 64;
        const size_t gofs = (size_t)(b * SEQ + qblk * 128 + r) * DM3 + h * DHEAD + c0;
        const uint4* qhp = (const uint4*)(qkvh + gofs);
        const uint4* qlp = (const uint4*)(qkvl + gofs);
        #pragma unroll
        for (int i = 0; i < 8; i++) {
            const int hofs = r * RSTR + c0 + 8 * i;
            *(uint4*)(smu + hofs / 2) = qhp[i];
            *(uint4*)(smu + (17408 + hofs) / 2) = qlp[i];
        }
    }
    __syncthreads();

    // ---- Extract Q fragments to registers
    unsigned qh[8][4], ql[8][4];
    {
        const int row = 16 * w + (lane & 15);
        const int cb  = 8 * (lane >> 4);
        #pragma unroll
        for (int ds = 0; ds < 8; ds++) {
            unsigned a = sbase + 2 * (row * RSTR + 16 * ds + cb);
            ldsm_x4(qh[ds][0], qh[ds][1], qh[ds][2], qh[ds][3], a);
            ldsm_x4(ql[ds][0], ql[ds][1], ql[ds][2], ql[ds][3], a + 2 * 17408);
        }
    }
    __syncthreads();   // all warps done with Q smem; stages may be overwritten

    const int ntiles = 2 * qblk + 2;

    // KV loader: 16 cpa16/thread, 16 consecutive lanes cover one 256B row.
    const int kv_r0 = tid >> 4;          // base row 0..15
    const int kv_ch = (tid & 15) * 8;    // chunk offset in halves
    auto issue_kv = [&](int kt, int stage) {
        const unsigned sb0 = sbase + 2 * stage * KVSTG;
        #pragma unroll
        for (int p = 0; p < 4; p++) {
            const __nv_bfloat16* plane_base =
                ((p & 1) ? qkvl : qkvh) + DMODEL + ((p >> 1) ? DMODEL : 0)
                + h * DHEAD + kv_ch;
            #pragma unroll
            for (int j = 0; j < 4; j++) {
                const int row = kv_r0 + 16 * j;
                cpa16(sb0 + 2 * (p * KVPLN + row * RSTR + kv_ch),
                      plane_base + (size_t)(b * SEQ + kt * 64 + row) * DM3);
            }
        }
        cpa_commit();
    };

    issue_kv(0, 0);
    issue_kv(1, 1);

    float o[16][4];
    #pragma unroll
    for (int nf = 0; nf < 16; nf++)
        #pragma unroll
        for (int i = 0; i < 4; i++) o[nf][i] = 0.f;
    float m0 = -1e30f, m1 = -1e30f, l0 = 0.f, l1 = 0.f;

    const int warp_row_max = qblk * 128 + 16 * w + 15;

    for (int kt = 0; kt < ntiles; kt++) {
        asm volatile("cp.async.wait_group 1;\n" ::: "memory");
        __syncthreads();

        const unsigned stg = sbase + 2 * (kt & 1) * KVSTG;

        if (kt * 64 <= warp_row_max) {
            float s[8][4];
            #pragma unroll
            for (int nf = 0; nf < 8; nf++)
                #pragma unroll
                for (int i = 0; i < 4; i++) s[nf][i] = 0.f;

            {
                const int krow   = (lane & 7) + 8 * (lane >> 4);
                const int kchunk = 8 * ((lane >> 3) & 1);
                #pragma unroll
                for (int ds = 0; ds < 8; ds++) {
                    #pragma unroll
                    for (int nfp = 0; nfp < 4; nfp++) {
                        unsigned a = stg + 2 * ((16 * nfp + krow) * RSTR
                                                + 16 * ds + kchunk);
                        unsigned bh0, bh1, bh2, bh3, bl0, bl1, bl2, bl3;
                        ldsm_x4(bh0, bh1, bh2, bh3, a);
                        ldsm_x4(bl0, bl1, bl2, bl3, a + 2 * KVPLN);
                        float* s0 = s[2 * nfp];
                        float* s1 = s[2 * nfp + 1];
                        mma_bf16(s0[0], s0[1], s0[2], s0[3],
                                 qh[ds][0], qh[ds][1], qh[ds][2], qh[ds][3], bh0, bh1);
                        mma_bf16(s0[0], s0[1], s0[2], s0[3],
                                 ql[ds][0], ql[ds][1], ql[ds][2], ql[ds][3], bh0, bh1);
                        mma_bf16(s0[0], s0[1], s0[2], s0[3],
                                 qh[ds][0], qh[ds][1], qh[ds][2], qh[ds][3], bl0, bl1);
                        mma_bf16(s1[0], s1[1], s1[2], s1[3],
                                 qh[ds][0], qh[ds][1], qh[ds][2], qh[ds][3], bh2, bh3);
                        mma_bf16(s1[0], s1[1], s1[2], s1[3],
                                 ql[ds][0], ql[ds][1], ql[ds][2], ql[ds][3], bh2, bh3);
                        mma_bf16(s1[0], s1[1], s1[2], s1[3],
                                 qh[ds][0], qh[ds][1], qh[ds][2], qh[ds][3], bl2, bl3);
                    }
                }
            }

            if (kt >= 2 * qblk) {
                const int row0 = qblk * 128 + 16 * w + g;
                #pragma unroll
                for (int nf = 0; nf < 8; nf++) {
                    const int col = kt * 64 + 8 * nf + 2 * q;
                    if (col     > row0)     s[nf][0] = -CUDART_INF_F;
                    if (col + 1 > row0)     s[nf][1] = -CUDART_INF_F;
                    if (col     > row0 + 8) s[nf][2] = -CUDART_INF_F;
                    if (col + 1 > row0 + 8) s[nf][3] = -CUDART_INF_F;
                }
            }

            float tm0 = -CUDART_INF_F, tm1 = -CUDART_INF_F;
            #pragma unroll
            for (int nf = 0; nf < 8; nf++) {
                tm0 = fmaxf(tm0, fmaxf(s[nf][0], s[nf][1]));
                tm1 = fmaxf(tm1, fmaxf(s[nf][2], s[nf][3]));
            }
            tm0 = fmaxf(tm0, __shfl_xor_sync(0xffffffffu, tm0, 1));
            tm0 = fmaxf(tm0, __shfl_xor_sync(0xffffffffu, tm0, 2));
            tm1 = fmaxf(tm1, __shfl_xor_sync(0xffffffffu, tm1, 1));
            tm1 = fmaxf(tm1, __shfl_xor_sync(0xffffffffu, tm1, 2));

            const float m0n = fmaxf(m0, tm0);
            const float m1n = fmaxf(m1, tm1);
            const float cr0 = exp2f((m0 - m0n) * ATT_C);
            const float cr1 = exp2f((m1 - m1n) * ATT_C);
            m0 = m0n; m1 = m1n;
            l0 *= cr0; l1 *= cr1;
            #pragma unroll
            for (int nf = 0; nf < 16; nf++) {
                o[nf][0] *= cr0; o[nf][1] *= cr0;
                o[nf][2] *= cr1; o[nf][3] *= cr1;
            }

            unsigned ph[8][2], pl[8][2];
            #pragma unroll
            for (int nf = 0; nf < 8; nf++) {
                float p0 = exp2f((s[nf][0] - m0) * ATT_C);
                float p1 = exp2f((s[nf][1] - m0) * ATT_C);
                float p2 = exp2f((s[nf][2] - m1) * ATT_C);
                float p3 = exp2f((s[nf][3] - m1) * ATT_C);
                l0 += p0 + p1;
                l1 += p2 + p3;
                __nv_bfloat162 h01 = __floats2bfloat162_rn(p0, p1);
                __nv_bfloat162 h23 = __floats2bfloat162_rn(p2, p3);
                __nv_bfloat162 e01 = __floats2bfloat162_rn(p0 - __low2float(h01),
                                                           p1 - __high2float(h01));
                __nv_bfloat162 e23 = __floats2bfloat162_rn(p2 - __low2float(h23),
                                                           p3 - __high2float(h23));
                ph[nf][0] = bf2u(h01); ph[nf][1] = bf2u(h23);
                pl[nf][0] = bf2u(e01); pl[nf][1] = bf2u(e23);
            }

            {
                const int vrow   = (lane & 15);
                const int vchunk = 8 * (lane >> 4);
                #pragma unroll
                for (int j = 0; j < 4; j++) {
                    const unsigned ah0 = ph[2 * j][0],     ah1 = ph[2 * j][1];
                    const unsigned ah2 = ph[2 * j + 1][0], ah3 = ph[2 * j + 1][1];
                    const unsigned al0 = pl[2 * j][0],     al1 = pl[2 * j][1];
                    const unsigned al2 = pl[2 * j + 1][0], al3 = pl[2 * j + 1][1];
                    #pragma unroll
                    for (int nfp = 0; nfp < 8; nfp++) {
                        unsigned a = stg + 2 * (2 * KVPLN + (16 * j + vrow) * RSTR
                                                + 16 * nfp + vchunk);
                        unsigned vh0, vh1, vh2, vh3, vl0, vl1, vl2, vl3;
                        ldsm_x4t(vh0, vh1, vh2, vh3, a);
                        ldsm_x4t(vl0, vl1, vl2, vl3, a + 2 * KVPLN);
                        float* o0 = o[2 * nfp];
                        float* o1 = o[2 * nfp + 1];
                        mma_bf16(o0[0], o0[1], o0[2], o0[3], ah0, ah1, ah2, ah3, vh0, vh1);
                        mma_bf16(o0[0], o0[1], o0[2], o0[3], al0, al1, al2, al3, vh0, vh1);
                        mma_bf16(o0[0], o0[1], o0[2], o0[3], ah0, ah1, ah2, ah3, vl0, vl1);
                        mma_bf16(o1[0], o1[1], o1[2], o1[3], ah0, ah1, ah2, ah3, vh2, vh3);
                        mma_bf16(o1[0], o1[1], o1[2], o1[3], al0, al1, al2, al3, vh2, vh3);
                        mma_bf16(o1[0], o1[1], o1[2], o1[3], ah0, ah1, ah2, ah3, vl2, vl3);
                    }
                }
            }
        }

        __syncthreads();   // all warps done reading stage kt&1
        if (kt + 2 < ntiles) issue_kv(kt + 2, kt & 1);
        else                 cpa_commit();   // keep group count uniform
    }

    l0 += __shfl_xor_sync(0xffffffffu, l0, 1);
    l0 += __shfl_xor_sync(0xffffffffu, l0, 2);
    l1 += __shfl_xor_sync(0xffffffffu, l1, 1);
    l1 += __shfl_xor_sync(0xffffffffu, l1, 2);
    const float inv0 = 1.f / l0;
    const float inv1 = 1.f / l1;

    // Epilogue: single fp16 plane
    const size_t row0 = (size_t)(b * SEQ + qblk * 128 + 16 * w + g);
    unsigned* oa = (unsigned*)(att + row0 * DMODEL + h * DHEAD);
    #pragma unroll
    for (int nf = 0; nf < 16; nf++) {
        const int ci = 4 * nf + q;
        oa[ci] = h2u(__floats2half2_rn(o[nf][0] * inv0, o[nf][1] * inv0));
        oa[ci + 4 * DMODEL] = h2u(__floats2half2_rn(o[nf][2] * inv1, o[nf][3] * inv1));
    }
}

// ---------------------------------------------------------------------------
// kernel_launch
// ---------------------------------------------------------------------------
extern "C" void kernel_launch(void* const* d_in, const int* in_sizes, int n_in,
                              void* d_out, int out_size)
{
    const float* x     = (const float*)d_in[0];
    const float* W_qkv = (const float*)d_in[1];
    const float* b_qkv = (const float*)d_in[2];
    const float* W_out = (const float*)d_in[3];
    const float* b_out = (const float*)d_in[4];
    float* out = (float*)d_out;

    __nv_bfloat16 *qh, *ql;
    __half *x16, *wq16, *wo16, *att16;
    cudaGetSymbolAddress((void**)&qh,   g_qkvh);
    cudaGetSymbolAddress((void**)&ql,   g_qkvl);
    cudaGetSymbolAddress((void**)&x16,  g_x16);
    cudaGetSymbolAddress((void**)&wq16, g_wqkvt16);
    cudaGetSymbolAddress((void**)&wo16, g_woutt16);
    cudaGetSymbolAddress((void**)&att16, g_att16);

    cudaFuncSetAttribute(flash_attn_tc_kernel,
                         cudaFuncAttributeMaxDynamicSharedMemorySize,
                         ATT_SMEM_BYTES);
    cudaFuncSetAttribute(gemm_fp16_bias_kernel,
                         cudaFuncAttributeMaxDynamicSharedMemorySize,
                         GEMM_SMEM_BYTES);

    // Prep: fp32 -> fp16 planes
    cvt_rm_kernel<<<(MTOT * DMODEL / 4 + 255) / 256, 256>>>(
        (const float4*)x, (uint2*)x16, MTOT * DMODEL / 4);
    cvt_tr_kernel<<<dim3(DM3 / 32, DMODEL / 32), 256>>>(
        W_qkv, wq16, DMODEL, DM3);
    cvt_tr_kernel<<<dim3(DMODEL / 32, DMODEL / 32), 256>>>(
        W_out, wo16, DMODEL, DMODEL);

    // 1) QKV GEMM (fp16) -> bf16 hi/lo planes for attention
    gemm_fp16_bias_kernel<<<dim3(DM3 / 128, MTOT / 128), 256, GEMM_SMEM_BYTES>>>(
        x16, wq16, b_qkv, nullptr, qh, ql, MTOT, DM3, DMODEL);

    // 2) Flash attention (triple-bf16, pipelined KV) -> fp16 plane
    flash_attn_tc_kernel<<<dim3(16, NHEADS, BATCH), 256, ATT_SMEM_BYTES>>>(
        qh, ql, att16);

    // 3) Output GEMM (fp16) -> fp32
    gemm_fp16_bias_kernel<<<dim3(DMODEL / 128, MTOT / 128), 256, GEMM_SMEM_BYTES>>>(
        att16, wo16, b_out, out, nullptr, nullptr, MTOT, DMODEL, DMODEL);
}

// round 14
// speedup vs baseline: 2.5734x; 1.0067x over previous
#include <cuda_runtime.h>
#include <cuda_bf16.h>
#include <cuda_fp16.h>
#include <math_constants.h>

#define BATCH   2
#define SEQ     2048
#define NHEADS  16
#define DHEAD   128
#define DMODEL  2048
#define DM3     6144
#define MTOT    4096

// Scratch (device globals)
__device__ __nv_bfloat16 g_qkvh[(size_t)MTOT * DM3];      // bf16 hi plane (Q,K)
__device__ __nv_bfloat16 g_qkvl[(size_t)MTOT * DM3];      // bf16 lo plane (Q,K)
__device__ __half        g_qkv16[(size_t)MTOT * DM3];     // fp16 plane (V)
__device__ __half        g_x16[(size_t)MTOT * DMODEL];
__device__ __half        g_wqkvt16[(size_t)DM3 * DMODEL]; // fp16 W_qkv^T [N][K]
__device__ __half        g_woutt16[(size_t)DMODEL * DMODEL];
__device__ __half        g_att16[(size_t)MTOT * DMODEL];

// ---------------------------------------------------------------------------
// Helpers
// ---------------------------------------------------------------------------
static __device__ __forceinline__ void mma_bf16(
    float& c0, float& c1, float& c2, float& c3,
    unsigned a0, unsigned a1, unsigned a2, unsigned a3,
    unsigned b0, unsigned b1)
{
    asm volatile(
        "mma.sync.aligned.m16n8k16.row.col.f32.bf16.bf16.f32 "
        "{%0,%1,%2,%3}, {%4,%5,%6,%7}, {%8,%9}, {%0,%1,%2,%3};\n"
        : "+f"(c0), "+f"(c1), "+f"(c2), "+f"(c3)
        : "r"(a0), "r"(a1), "r"(a2), "r"(a3), "r"(b0), "r"(b1));
}
static __device__ __forceinline__ void mma_fp16(
    float& c0, float& c1, float& c2, float& c3,
    unsigned a0, unsigned a1, unsigned a2, unsigned a3,
    unsigned b0, unsigned b1)
{
    asm volatile(
        "mma.sync.aligned.m16n8k16.row.col.f32.f16.f16.f32 "
        "{%0,%1,%2,%3}, {%4,%5,%6,%7}, {%8,%9}, {%0,%1,%2,%3};\n"
        : "+f"(c0), "+f"(c1), "+f"(c2), "+f"(c3)
        : "r"(a0), "r"(a1), "r"(a2), "r"(a3), "r"(b0), "r"(b1));
}
static __device__ __forceinline__ void ldsm_x4(
    unsigned& r0, unsigned& r1, unsigned& r2, unsigned& r3, unsigned addr)
{
    asm volatile("ldmatrix.sync.aligned.m8n8.x4.shared.b16 {%0,%1,%2,%3}, [%4];\n"
                 : "=r"(r0), "=r"(r1), "=r"(r2), "=r"(r3) : "r"(addr));
}
static __device__ __forceinline__ void ldsm_x4t(
    unsigned& r0, unsigned& r1, unsigned& r2, unsigned& r3, unsigned addr)
{
    asm volatile("ldmatrix.sync.aligned.m8n8.x4.trans.shared.b16 {%0,%1,%2,%3}, [%4];\n"
                 : "=r"(r0), "=r"(r1), "=r"(r2), "=r"(r3) : "r"(addr));
}
static __device__ __forceinline__ unsigned bf2u(__nv_bfloat162 v) {
    return *reinterpret_cast<unsigned*>(&v);
}
static __device__ __forceinline__ unsigned h2u(__half2 v) {
    return *reinterpret_cast<unsigned*>(&v);
}
static __device__ __forceinline__ void cpa16(unsigned saddr, const void* g) {
    asm volatile("cp.async.cg.shared.global [%0], [%1], 16;\n"
                 :: "r"(saddr), "l"(g));
}
static __device__ __forceinline__ void cpa_commit() {
    asm volatile("cp.async.commit_group;\n" ::: "memory");
}

// ---------------------------------------------------------------------------
// Prep kernels: fp32 -> fp16
// ---------------------------------------------------------------------------
__global__ __launch_bounds__(256) void cvt_rm_kernel(
    const float4* __restrict__ src, uint2* __restrict__ d, int n4)
{
    int i = blockIdx.x * 256 + threadIdx.x;
    if (i < n4) {
        float4 f = src[i];
        uint2 o;
        o.x = h2u(__floats2half2_rn(f.x, f.y));
        o.y = h2u(__floats2half2_rn(f.z, f.w));
        d[i] = o;
    }
}

__global__ __launch_bounds__(256) void cvt_tr_kernel(
    const float* __restrict__ W, __half* __restrict__ wt, int K, int N)
{
    __shared__ float tile[32][33];
    const int n0 = blockIdx.x * 32, k0 = blockIdx.y * 32;
    const int tx = threadIdx.x & 31, ty = threadIdx.x >> 5;
    #pragma unroll
    for (int i = 0; i < 32; i += 8)
        tile[ty + i][tx] = W[(size_t)(k0 + ty + i) * N + (n0 + tx)];
    __syncthreads();
    #pragma unroll
    for (int i = 0; i < 32; i += 8)
        wt[(size_t)(n0 + ty + i) * K + (k0 + tx)] = __float2half_rn(tile[tx][ty + i]);
}

// ---------------------------------------------------------------------------
// fp16 GEMM: C = A[M,K] @ B^T[N,K] + bias, fp32 accumulate.
// Block 128x128, ktile 64, 256 threads = 8 warps (4m x 2n), warp tile 32x64.
// Row stride GST=72 halves (144B, 16B-aligned, conflict-free ldmatrix).
// 3-stage cp.async ring (wait_group 1), 108KB -> 2 CTAs/SM.
// Outputs: fp32 Cf, or (bf16 Ch + bf16 Cl + fp16 C16) planes.
// ---------------------------------------------------------------------------
#define GST 72                       // halves per smem row (64 + 8 pad)
#define PLN (128 * GST)              // plane size in halves (9216)
#define STG_H (2 * PLN)              // stage halves (18432) = 36864 B
#define NSTG 3
#define GEMM_SMEM_BYTES (NSTG * STG_H * 2)   // 110592

__global__ __launch_bounds__(256, 2) void gemm_fp16_bias_kernel(
    const __half* __restrict__ A, const __half* __restrict__ B,
    const float* __restrict__ bias,
    float* __restrict__ Cf,
    __nv_bfloat16* __restrict__ Ch, __nv_bfloat16* __restrict__ Cl,
    __half* __restrict__ C16,
    int M, int N, int K)
{
    extern __shared__ __half sm[];
    const unsigned sb = (unsigned)__cvta_generic_to_shared(sm);

    const int t = threadIdx.x, lane = t & 31, wid = t >> 5;
    const int bm = blockIdx.y, bn = blockIdx.x;
    const int warp_m = wid >> 1, warp_n = wid & 1;

    const int lr = t >> 1;              // row 0..127
    const int ls = (t & 1) * 32;        // halves 0 or 32
    const __half* Ag = A + (size_t)(bm * 128 + lr) * K + ls;
    const __half* Bg = B + (size_t)(bn * 128 + lr) * K + ls;
    const unsigned sAd = sb + 2 * (lr * GST + ls);

    float c[2][8][4];
    #pragma unroll
    for (int mf = 0; mf < 2; mf++)
        #pragma unroll
        for (int nf = 0; nf < 8; nf++)
            #pragma unroll
            for (int i = 0; i < 4; i++) c[mf][nf][i] = 0.f;

    const int nK = K / 64;

    auto issue_stage = [&](int kt) {
        const int go = kt * 64;
        const unsigned d = sAd + 2 * (kt % NSTG) * STG_H;
        cpa16(d,                 Ag + go);
        cpa16(d + 16,            Ag + go + 8);
        cpa16(d + 32,            Ag + go + 16);
        cpa16(d + 48,            Ag + go + 24);
        cpa16(d + 2 * PLN,       Bg + go);
        cpa16(d + 2 * PLN + 16,  Bg + go + 8);
        cpa16(d + 2 * PLN + 32,  Bg + go + 16);
        cpa16(d + 2 * PLN + 48,  Bg + go + 24);
        cpa_commit();
    };

    issue_stage(0);
    issue_stage(1);

    for (int kt = 0; kt < nK; kt++) {
        asm volatile("cp.async.wait_group 1;\n" ::: "memory");
        __syncthreads();

        if (kt + 2 < nK) issue_stage(kt + 2);

        const unsigned base = sb + 2 * (kt % NSTG) * STG_H;
        #pragma unroll
        for (int s = 0; s < 4; s++) {
            unsigned ah[2][4];
            #pragma unroll
            for (int mf = 0; mf < 2; mf++) {
                const int row = warp_m * 32 + mf * 16 + (lane & 15);
                const unsigned a = base + 2 * (row * GST + 16 * s + 8 * (lane >> 4));
                ldsm_x4(ah[mf][0], ah[mf][1], ah[mf][2], ah[mf][3], a);
            }
            #pragma unroll
            for (int nfp = 0; nfp < 4; nfp++) {
                const int nrow = warp_n * 64 + nfp * 16 + (lane & 7) + 8 * (lane >> 4);
                const unsigned a = base + 2 * (PLN + nrow * GST
                                               + 16 * s + 8 * ((lane >> 3) & 1));
                unsigned b0, b1, b2, b3;
                ldsm_x4(b0, b1, b2, b3, a);
                #pragma unroll
                for (int mf = 0; mf < 2; mf++) {
                    float* c0 = c[mf][2 * nfp];
                    float* c1 = c[mf][2 * nfp + 1];
                    mma_fp16(c0[0], c0[1], c0[2], c0[3],
                             ah[mf][0], ah[mf][1], ah[mf][2], ah[mf][3], b0, b1);
                    mma_fp16(c1[0], c1[1], c1[2], c1[3],
                             ah[mf][0], ah[mf][1], ah[mf][2], ah[mf][3], b2, b3);
                }
            }
        }
    }

    // Epilogue
    const int g = lane >> 2, q = lane & 3;
    const int crow0 = bm * 128 + warp_m * 32 + g;
    const int ccol0 = bn * 128 + warp_n * 64 + 2 * q;
    if (Cf) {
        #pragma unroll
        for (int nf = 0; nf < 8; nf++) {
            const int col = ccol0 + nf * 8;
            const float bx = bias[col];
            const float by = bias[col + 1];
            #pragma unroll
            for (int mf = 0; mf < 2; mf++) {
                const int row = crow0 + mf * 16;
                *(float2*)(Cf + (size_t)row * N + col) =
                    make_float2(c[mf][nf][0] + bx, c[mf][nf][1] + by);
                *(float2*)(Cf + (size_t)(row + 8) * N + col) =
                    make_float2(c[mf][nf][2] + bx, c[mf][nf][3] + by);
            }
        }
    } else {
        unsigned* Chu = (unsigned*)Ch;
        unsigned* Clu = (unsigned*)Cl;
        unsigned* C16u = (unsigned*)C16;
        const int nh = N / 2;
        #pragma unroll
        for (int nf = 0; nf < 8; nf++) {
            const int col = ccol0 + nf * 8;
            const float bx = bias[col];
            const float by = bias[col + 1];
            #pragma unroll
            for (int mf = 0; mf < 2; mf++) {
                const int row = crow0 + mf * 16;
                float v0 = c[mf][nf][0] + bx, v1 = c[mf][nf][1] + by;
                float w0 = c[mf][nf][2] + bx, w1 = c[mf][nf][3] + by;
                __nv_bfloat162 vh = __floats2bfloat162_rn(v0, v1);
                __nv_bfloat162 wh = __floats2bfloat162_rn(w0, w1);
                __nv_bfloat162 vl = __floats2bfloat162_rn(v0 - __low2float(vh),
                                                          v1 - __high2float(vh));
                __nv_bfloat162 wl = __floats2bfloat162_rn(w0 - __low2float(wh),
                                                          w1 - __high2float(wh));
                const size_t i0 = (size_t)row * nh + col / 2;
                const size_t i1 = (size_t)(row + 8) * nh + col / 2;
                Chu[i0] = bf2u(vh);
                Clu[i0] = bf2u(vl);
                Chu[i1] = bf2u(wh);
                Clu[i1] = bf2u(wl);
                C16u[i0] = h2u(__floats2half2_rn(v0, v1));
                C16u[i1] = h2u(__floats2half2_rn(w0, w1));
            }
        }
    }
}

// ---------------------------------------------------------------------------
// Flash attention (causal): QK^T triple-bf16, PV single-fp16.
// 2-stage cp.async KV ring; stage = KH | KL | V16 (3 planes, 64 x 136 halves).
// Output: fp16 plane.
// ---------------------------------------------------------------------------
#define ATT_C 0.12751666769323707f  // (1/sqrt(128)) * log2(e)
#define RSTR  136
#define KVPLN (64 * RSTR)            // 8704 halves per plane
#define KVSTG (3 * KVPLN)            // 26112 halves per stage
#define ATT_SMEM_BYTES (2 * KVSTG * 2)   // 104448

__global__ __launch_bounds__(256) void flash_attn_tc_kernel(
    const __nv_bfloat16* __restrict__ qkvh, const __nv_bfloat16* __restrict__ qkvl,
    const __half* __restrict__ qkv16,
    __half* __restrict__ att)
{
    extern __shared__ unsigned smu[];
    const unsigned sbase = (unsigned)__cvta_generic_to_shared(smu);

    const int qblk = blockIdx.x;
    const int h    = blockIdx.y;
    const int b    = blockIdx.z;
    const int tid  = threadIdx.x;
    const int lane = tid & 31;
    const int w    = tid >> 5;
    const int g    = lane >> 2;
    const int q    = lane & 3;

    // ---- Stage Q planes (QH at half 0, QL at half 17408; overlays KV ring)
    {
        const int r  = tid >> 1;
        const int c0 = (tid & 1) * 64;
        const size_t gofs = (size_t)(b * SEQ + qblk * 128 + r) * DM3 + h * DHEAD + c0;
        const uint4* qhp = (const uint4*)(qkvh + gofs);
        const uint4* qlp = (const uint4*)(qkvl + gofs);
        #pragma unroll
        for (int i = 0; i < 8; i++) {
            const int hofs = r * RSTR + c0 + 8 * i;
            *(uint4*)(smu + hofs / 2) = qhp[i];
            *(uint4*)(smu + (17408 + hofs) / 2) = qlp[i];
        }
    }
    __syncthreads();

    unsigned qh[8][4], ql[8][4];
    {
        const int row = 16 * w + (lane & 15);
        const int cb  = 8 * (lane >> 4);
        #pragma unroll
        for (int ds = 0; ds < 8; ds++) {
            unsigned a = sbase + 2 * (row * RSTR + 16 * ds + cb);
            ldsm_x4(qh[ds][0], qh[ds][1], qh[ds][2], qh[ds][3], a);
            ldsm_x4(ql[ds][0], ql[ds][1], ql[ds][2], ql[ds][3], a + 2 * 17408);
        }
    }
    __syncthreads();

    const int ntiles = 2 * qblk + 2;

    // KV loader: 12 cpa16/thread (3 planes x 4 rows); 16 lanes cover one row.
    const int kv_r0 = tid >> 4;
    const int kv_ch = (tid & 15) * 8;
    auto issue_kv = [&](int kt, int stage) {
        const unsigned sb0 = sbase + 2 * stage * KVSTG;
        #pragma unroll
        for (int p = 0; p < 3; p++) {
            const __nv_bfloat16* plane_base =
                (p == 0 ? qkvh + DMODEL
                        : (p == 1 ? qkvl + DMODEL
                                  : (const __nv_bfloat16*)qkv16 + 2 * DMODEL))
                + h * DHEAD + kv_ch;
            #pragma unroll
            for (int j = 0; j < 4; j++) {
                const int row = kv_r0 + 16 * j;
                cpa16(sb0 + 2 * (p * KVPLN + row * RSTR + kv_ch),
                      plane_base + (size_t)(b * SEQ + kt * 64 + row) * DM3);
            }
        }
        cpa_commit();
    };

    issue_kv(0, 0);
    issue_kv(1, 1);

    float o[16][4];
    #pragma unroll
    for (int nf = 0; nf < 16; nf++)
        #pragma unroll
        for (int i = 0; i < 4; i++) o[nf][i] = 0.f;
    float m0 = -1e30f, m1 = -1e30f, l0 = 0.f, l1 = 0.f;

    const int warp_row_max = qblk * 128 + 16 * w + 15;

    for (int kt = 0; kt < ntiles; kt++) {
        asm volatile("cp.async.wait_group 1;\n" ::: "memory");
        __syncthreads();

        const unsigned stg = sbase + 2 * (kt & 1) * KVSTG;

        if (kt * 64 <= warp_row_max) {
            float s[8][4];
            #pragma unroll
            for (int nf = 0; nf < 8; nf++)
                #pragma unroll
                for (int i = 0; i < 4; i++) s[nf][i] = 0.f;

            {
                const int krow   = (lane & 7) + 8 * (lane >> 4);
                const int kchunk = 8 * ((lane >> 3) & 1);
                #pragma unroll
                for (int ds = 0; ds < 8; ds++) {
                    #pragma unroll
                    for (int nfp = 0; nfp < 4; nfp++) {
                        unsigned a = stg + 2 * ((16 * nfp + krow) * RSTR
                                                + 16 * ds + kchunk);
                        unsigned bh0, bh1, bh2, bh3, bl0, bl1, bl2, bl3;
                        ldsm_x4(bh0, bh1, bh2, bh3, a);
                        ldsm_x4(bl0, bl1, bl2, bl3, a + 2 * KVPLN);
                        float* s0 = s[2 * nfp];
                        float* s1 = s[2 * nfp + 1];
                        mma_bf16(s0[0], s0[1], s0[2], s0[3],
                                 qh[ds][0], qh[ds][1], qh[ds][2], qh[ds][3], bh0, bh1);
                        mma_bf16(s0[0], s0[1], s0[2], s0[3],
                                 ql[ds][0], ql[ds][1], ql[ds][2], ql[ds][3], bh0, bh1);
                        mma_bf16(s0[0], s0[1], s0[2], s0[3],
                                 qh[ds][0], qh[ds][1], qh[ds][2], qh[ds][3], bl0, bl1);
                        mma_bf16(s1[0], s1[1], s1[2], s1[3],
                                 qh[ds][0], qh[ds][1], qh[ds][2], qh[ds][3], bh2, bh3);
                        mma_bf16(s1[0], s1[1], s1[2], s1[3],
                                 ql[ds][0], ql[ds][1], ql[ds][2], ql[ds][3], bh2, bh3);
                        mma_bf16(s1[0], s1[1], s1[2], s1[3],
                                 qh[ds][0], qh[ds][1], qh[ds][2], qh[ds][3], bl2, bl3);
                    }
                }
            }

            if (kt >= 2 * qblk) {
                const int row0 = qblk * 128 + 16 * w + g;
                #pragma unroll
                for (int nf = 0; nf < 8; nf++) {
                    const int col = kt * 64 + 8 * nf + 2 * q;
                    if (col     > row0)     s[nf][0] = -CUDART_INF_F;
                    if (col + 1 > row0)     s[nf][1] = -CUDART_INF_F;
                    if (col     > row0 + 8) s[nf][2] = -CUDART_INF_F;
                    if (col + 1 > row0 + 8) s[nf][3] = -CUDART_INF_F;
                }
            }

            float tm0 = -CUDART_INF_F, tm1 = -CUDART_INF_F;
            #pragma unroll
            for (int nf = 0; nf < 8; nf++) {
                tm0 = fmaxf(tm0, fmaxf(s[nf][0], s[nf][1]));
                tm1 = fmaxf(tm1, fmaxf(s[nf][2], s[nf][3]));
            }
            tm0 = fmaxf(tm0, __shfl_xor_sync(0xffffffffu, tm0, 1));
            tm0 = fmaxf(tm0, __shfl_xor_sync(0xffffffffu, tm0, 2));
            tm1 = fmaxf(tm1, __shfl_xor_sync(0xffffffffu, tm1, 1));
            tm1 = fmaxf(tm1, __shfl_xor_sync(0xffffffffu, tm1, 2));

            const float m0n = fmaxf(m0, tm0);
            const float m1n = fmaxf(m1, tm1);
            const float cr0 = exp2f((m0 - m0n) * ATT_C);
            const float cr1 = exp2f((m1 - m1n) * ATT_C);
            m0 = m0n; m1 = m1n;
            l0 *= cr0; l1 *= cr1;
            #pragma unroll
            for (int nf = 0; nf < 16; nf++) {
                o[nf][0] *= cr0; o[nf][1] *= cr0;
                o[nf][2] *= cr1; o[nf][3] *= cr1;
            }

            unsigned ph[8][2];
            #pragma unroll
            for (int nf = 0; nf < 8; nf++) {
                float p0 = exp2f((s[nf][0] - m0) * ATT_C);
                float p1 = exp2f((s[nf][1] - m0) * ATT_C);
                float p2 = exp2f((s[nf][2] - m1) * ATT_C);
                float p3 = exp2f((s[nf][3] - m1) * ATT_C);
                l0 += p0 + p1;
                l1 += p2 + p3;
                ph[nf][0] = h2u(__floats2half2_rn(p0, p1));
                ph[nf][1] = h2u(__floats2half2_rn(p2, p3));
            }

            // O += P V (single fp16)
            {
                const int vrow   = (lane & 15);
                const int vchunk = 8 * (lane >> 4);
                #pragma unroll
                for (int j = 0; j < 4; j++) {
                    const unsigned a0 = ph[2 * j][0],     a1 = ph[2 * j][1];
                    const unsigned a2 = ph[2 * j + 1][0], a3 = ph[2 * j + 1][1];
                    #pragma unroll
                    for (int nfp = 0; nfp < 8; nfp++) {
                        unsigned a = stg + 2 * (2 * KVPLN + (16 * j + vrow) * RSTR
                                                + 16 * nfp + vchunk);
                        unsigned v0, v1, v2, v3;
                        ldsm_x4t(v0, v1, v2, v3, a);
                        float* o0 = o[2 * nfp];
                        float* o1 = o[2 * nfp + 1];
                        mma_fp16(o0[0], o0[1], o0[2], o0[3], a0, a1, a2, a3, v0, v1);
                        mma_fp16(o1[0], o1[1], o1[2], o1[3], a0, a1, a2, a3, v2, v3);
                    }
                }
            }
        }

        __syncthreads();   // all warps done reading stage kt&1
        if (kt + 2 < ntiles) issue_kv(kt + 2, kt & 1);
        else                 cpa_commit();   // uniform group count
    }

    l0 += __shfl_xor_sync(0xffffffffu, l0, 1);
    l0 += __shfl_xor_sync(0xffffffffu, l0, 2);
    l1 += __shfl_xor_sync(0xffffffffu, l1, 1);
    l1 += __shfl_xor_sync(0xffffffffu, l1, 2);
    const float inv0 = 1.f / l0;
    const float inv1 = 1.f / l1;

    const size_t row0 = (size_t)(b * SEQ + qblk * 128 + 16 * w + g);
    unsigned* oa = (unsigned*)(att + row0 * DMODEL + h * DHEAD);
    #pragma unroll
    for (int nf = 0; nf < 16; nf++) {
        const int ci = 4 * nf + q;
        oa[ci] = h2u(__floats2half2_rn(o[nf][0] * inv0, o[nf][1] * inv0));
        oa[ci + 4 * DMODEL] = h2u(__floats2half2_rn(o[nf][2] * inv1, o[nf][3] * inv1));
    }
}

// ---------------------------------------------------------------------------
// kernel_launch
// ---------------------------------------------------------------------------
extern "C" void kernel_launch(void* const* d_in, const int* in_sizes, int n_in,
                              void* d_out, int out_size)
{
    const float* x     = (const float*)d_in[0];
    const float* W_qkv = (const float*)d_in[1];
    const float* b_qkv = (const float*)d_in[2];
    const float* W_out = (const float*)d_in[3];
    const float* b_out = (const float*)d_in[4];
    float* out = (float*)d_out;

    __nv_bfloat16 *qh, *ql;
    __half *qv16, *x16, *wq16, *wo16, *att16;
    cudaGetSymbolAddress((void**)&qh,   g_qkvh);
    cudaGetSymbolAddress((void**)&ql,   g_qkvl);
    cudaGetSymbolAddress((void**)&qv16, g_qkv16);
    cudaGetSymbolAddress((void**)&x16,  g_x16);
    cudaGetSymbolAddress((void**)&wq16, g_wqkvt16);
    cudaGetSymbolAddress((void**)&wo16, g_woutt16);
    cudaGetSymbolAddress((void**)&att16, g_att16);

    cudaFuncSetAttribute(flash_attn_tc_kernel,
                         cudaFuncAttributeMaxDynamicSharedMemorySize,
                         ATT_SMEM_BYTES);
    cudaFuncSetAttribute(gemm_fp16_bias_kernel,
                         cudaFuncAttributeMaxDynamicSharedMemorySize,
                         GEMM_SMEM_BYTES);

    // Prep: fp32 -> fp16
    cvt_rm_kernel<<<(MTOT * DMODEL / 4 + 255) / 256, 256>>>(
        (const float4*)x, (uint2*)x16, MTOT * DMODEL / 4);
    cvt_tr_kernel<<<dim3(DM3 / 32, DMODEL / 32), 256>>>(
        W_qkv, wq16, DMODEL, DM3);
    cvt_tr_kernel<<<dim3(DMODEL / 32, DMODEL / 32), 256>>>(
        W_out, wo16, DMODEL, DMODEL);

    // 1) QKV GEMM (fp16) -> bf16 hi/lo planes + fp16 plane
    gemm_fp16_bias_kernel<<<dim3(DM3 / 128, MTOT / 128), 256, GEMM_SMEM_BYTES>>>(
        x16, wq16, b_qkv, nullptr, qh, ql, qv16, MTOT, DM3, DMODEL);

    // 2) Flash attention (QK triple-bf16, PV fp16) -> fp16 plane
    flash_attn_tc_kernel<<<dim3(16, NHEADS, BATCH), 256, ATT_SMEM_BYTES>>>(
        qh, ql, qv16, att16);

    // 3) Output GEMM (fp16) -> fp32
    gemm_fp16_bias_kernel<<<dim3(DMODEL / 128, MTOT / 128), 256, GEMM_SMEM_BYTES>>>(
        att16, wo16, b_out, out, nullptr, nullptr, nullptr, MTOT, DMODEL, DMODEL);
}

// round 15
// speedup vs baseline: 2.7511x; 1.0691x over previous
#include <cuda_runtime.h>
#include <cuda_bf16.h>
#include <cuda_fp16.h>
#include <math_constants.h>

#define BATCH   2
#define SEQ     2048
#define NHEADS  16
#define DHEAD   128
#define DMODEL  2048
#define DM3     6144
#define MTOT    4096

// Scratch (device globals)
__device__ __nv_bfloat16 g_qkvh[(size_t)MTOT * DM3];      // bf16 hi plane (Q,K)
__device__ __nv_bfloat16 g_qkvl[(size_t)MTOT * DM3];      // bf16 lo plane (Q,K)
__device__ __half        g_qkv16[(size_t)MTOT * DM3];     // fp16 plane (V)
__device__ __half        g_x16[(size_t)MTOT * DMODEL];
__device__ __half        g_wqkvt16[(size_t)DM3 * DMODEL]; // fp16 W_qkv^T [N][K]
__device__ __half        g_woutt16[(size_t)DMODEL * DMODEL];
__device__ __half        g_att16[(size_t)MTOT * DMODEL];

// ---------------------------------------------------------------------------
// Helpers
// ---------------------------------------------------------------------------
static __device__ __forceinline__ void mma_bf16(
    float& c0, float& c1, float& c2, float& c3,
    unsigned a0, unsigned a1, unsigned a2, unsigned a3,
    unsigned b0, unsigned b1)
{
    asm volatile(
        "mma.sync.aligned.m16n8k16.row.col.f32.bf16.bf16.f32 "
        "{%0,%1,%2,%3}, {%4,%5,%6,%7}, {%8,%9}, {%0,%1,%2,%3};\n"
        : "+f"(c0), "+f"(c1), "+f"(c2), "+f"(c3)
        : "r"(a0), "r"(a1), "r"(a2), "r"(a3), "r"(b0), "r"(b1));
}
static __device__ __forceinline__ void mma_fp16(
    float& c0, float& c1, float& c2, float& c3,
    unsigned a0, unsigned a1, unsigned a2, unsigned a3,
    unsigned b0, unsigned b1)
{
    asm volatile(
        "mma.sync.aligned.m16n8k16.row.col.f32.f16.f16.f32 "
        "{%0,%1,%2,%3}, {%4,%5,%6,%7}, {%8,%9}, {%0,%1,%2,%3};\n"
        : "+f"(c0), "+f"(c1), "+f"(c2), "+f"(c3)
        : "r"(a0), "r"(a1), "r"(a2), "r"(a3), "r"(b0), "r"(b1));
}
static __device__ __forceinline__ void ldsm_x4(
    unsigned& r0, unsigned& r1, unsigned& r2, unsigned& r3, unsigned addr)
{
    asm volatile("ldmatrix.sync.aligned.m8n8.x4.shared.b16 {%0,%1,%2,%3}, [%4];\n"
                 : "=r"(r0), "=r"(r1), "=r"(r2), "=r"(r3) : "r"(addr));
}
static __device__ __forceinline__ void ldsm_x4t(
    unsigned& r0, unsigned& r1, unsigned& r2, unsigned& r3, unsigned addr)
{
    asm volatile("ldmatrix.sync.aligned.m8n8.x4.trans.shared.b16 {%0,%1,%2,%3}, [%4];\n"
                 : "=r"(r0), "=r"(r1), "=r"(r2), "=r"(r3) : "r"(addr));
}
static __device__ __forceinline__ unsigned bf2u(__nv_bfloat162 v) {
    return *reinterpret_cast<unsigned*>(&v);
}
static __device__ __forceinline__ unsigned h2u(__half2 v) {
    return *reinterpret_cast<unsigned*>(&v);
}
static __device__ __forceinline__ void cpa16(unsigned saddr, const void* g) {
    asm volatile("cp.async.cg.shared.global [%0], [%1], 16;\n"
                 :: "r"(saddr), "l"(g));
}
static __device__ __forceinline__ void cpa_commit() {
    asm volatile("cp.async.commit_group;\n" ::: "memory");
}

// ---------------------------------------------------------------------------
// Prep kernels: fp32 -> fp16
// ---------------------------------------------------------------------------
__global__ __launch_bounds__(256) void cvt_rm_kernel(
    const float4* __restrict__ src, uint2* __restrict__ d, int n4)
{
    int i = blockIdx.x * 256 + threadIdx.x;
    if (i < n4) {
        float4 f = src[i];
        uint2 o;
        o.x = h2u(__floats2half2_rn(f.x, f.y));
        o.y = h2u(__floats2half2_rn(f.z, f.w));
        d[i] = o;
    }
}

__global__ __launch_bounds__(256) void cvt_tr_kernel(
    const float* __restrict__ W, __half* __restrict__ wt, int K, int N)
{
    __shared__ float tile[32][33];
    const int n0 = blockIdx.x * 32, k0 = blockIdx.y * 32;
    const int tx = threadIdx.x & 31, ty = threadIdx.x >> 5;
    #pragma unroll
    for (int i = 0; i < 32; i += 8)
        tile[ty + i][tx] = W[(size_t)(k0 + ty + i) * N + (n0 + tx)];
    __syncthreads();
    #pragma unroll
    for (int i = 0; i < 32; i += 8)
        wt[(size_t)(n0 + ty + i) * K + (k0 + tx)] = __float2half_rn(tile[tx][ty + i]);
}

// ---------------------------------------------------------------------------
// fp16 GEMM (round-13 measured-best config): C = A[M,K] @ B^T[N,K] + bias.
// Block 128x128, ktile 32, 256 threads = 8 warps (4m x 2n), warp tile 32x64.
// GST=40 halves, 4-stage cp.async ring (wait_group 2, kt&3), 80KB, 2 CTAs/SM.
// Outputs: fp32 Cf, or (bf16 Ch + bf16 Cl + fp16 C16) planes.
// ---------------------------------------------------------------------------
#define GST 40                       // halves per smem row (32 + 8 pad)
#define PLN (128 * GST)              // plane size in halves (5120)
#define STG_H (2 * PLN)              // stage halves (10240) = 20480 B
#define NSTG 4
#define GEMM_SMEM_BYTES (NSTG * STG_H * 2)   // 81920

__global__ __launch_bounds__(256, 2) void gemm_fp16_bias_kernel(
    const __half* __restrict__ A, const __half* __restrict__ B,
    const float* __restrict__ bias,
    float* __restrict__ Cf,
    __nv_bfloat16* __restrict__ Ch, __nv_bfloat16* __restrict__ Cl,
    __half* __restrict__ C16,
    int M, int N, int K)
{
    extern __shared__ __half sm[];
    const unsigned sb = (unsigned)__cvta_generic_to_shared(sm);

    const int t = threadIdx.x, lane = t & 31, wid = t >> 5;
    const int bm = blockIdx.y, bn = blockIdx.x;
    const int warp_m = wid >> 1, warp_n = wid & 1;

    const int lr = t >> 1;
    const int ls = (t & 1) * 16;
    const __half* Ag = A + (size_t)(bm * 128 + lr) * K + ls;
    const __half* Bg = B + (size_t)(bn * 128 + lr) * K + ls;
    const unsigned sAd = sb + 2 * (lr * GST + ls);

    float c[2][8][4];
    #pragma unroll
    for (int mf = 0; mf < 2; mf++)
        #pragma unroll
        for (int nf = 0; nf < 8; nf++)
            #pragma unroll
            for (int i = 0; i < 4; i++) c[mf][nf][i] = 0.f;

    const int nK = K / 32;

    auto issue_stage = [&](int kt) {
        const int go = kt * 32;
        const unsigned d = sAd + 2 * (kt & 3) * STG_H;
        cpa16(d,                 Ag + go);
        cpa16(d + 16,            Ag + go + 8);
        cpa16(d + 2 * PLN,       Bg + go);
        cpa16(d + 2 * PLN + 16,  Bg + go + 8);
        cpa_commit();
    };

    issue_stage(0);
    issue_stage(1);
    issue_stage(2);

    for (int kt = 0; kt < nK; kt++) {
        asm volatile("cp.async.wait_group 2;\n" ::: "memory");
        __syncthreads();

        if (kt + 3 < nK) issue_stage(kt + 3);

        const unsigned base = sb + 2 * (kt & 3) * STG_H;
        #pragma unroll
        for (int s = 0; s < 2; s++) {
            unsigned ah[2][4];
            #pragma unroll
            for (int mf = 0; mf < 2; mf++) {
                const int row = warp_m * 32 + mf * 16 + (lane & 15);
                const unsigned a = base + 2 * (row * GST + 16 * s + 8 * (lane >> 4));
                ldsm_x4(ah[mf][0], ah[mf][1], ah[mf][2], ah[mf][3], a);
            }
            #pragma unroll
            for (int nfp = 0; nfp < 4; nfp++) {
                const int nrow = warp_n * 64 + nfp * 16 + (lane & 7) + 8 * (lane >> 4);
                const unsigned a = base + 2 * (PLN + nrow * GST
                                               + 16 * s + 8 * ((lane >> 3) & 1));
                unsigned b0, b1, b2, b3;
                ldsm_x4(b0, b1, b2, b3, a);
                #pragma unroll
                for (int mf = 0; mf < 2; mf++) {
                    float* c0 = c[mf][2 * nfp];
                    float* c1 = c[mf][2 * nfp + 1];
                    mma_fp16(c0[0], c0[1], c0[2], c0[3],
                             ah[mf][0], ah[mf][1], ah[mf][2], ah[mf][3], b0, b1);
                    mma_fp16(c1[0], c1[1], c1[2], c1[3],
                             ah[mf][0], ah[mf][1], ah[mf][2], ah[mf][3], b2, b3);
                }
            }
        }
    }

    // Epilogue
    const int g = lane >> 2, q = lane & 3;
    const int crow0 = bm * 128 + warp_m * 32 + g;
    const int ccol0 = bn * 128 + warp_n * 64 + 2 * q;
    if (Cf) {
        #pragma unroll
        for (int nf = 0; nf < 8; nf++) {
            const int col = ccol0 + nf * 8;
            const float bx = bias[col];
            const float by = bias[col + 1];
            #pragma unroll
            for (int mf = 0; mf < 2; mf++) {
                const int row = crow0 + mf * 16;
                *(float2*)(Cf + (size_t)row * N + col) =
                    make_float2(c[mf][nf][0] + bx, c[mf][nf][1] + by);
                *(float2*)(Cf + (size_t)(row + 8) * N + col) =
                    make_float2(c[mf][nf][2] + bx, c[mf][nf][3] + by);
            }
        }
    } else {
        unsigned* Chu = (unsigned*)Ch;
        unsigned* Clu = (unsigned*)Cl;
        unsigned* C16u = (unsigned*)C16;
        const int nh = N / 2;
        #pragma unroll
        for (int nf = 0; nf < 8; nf++) {
            const int col = ccol0 + nf * 8;
            const float bx = bias[col];
            const float by = bias[col + 1];
            #pragma unroll
            for (int mf = 0; mf < 2; mf++) {
                const int row = crow0 + mf * 16;
                float v0 = c[mf][nf][0] + bx, v1 = c[mf][nf][1] + by;
                float w0 = c[mf][nf][2] + bx, w1 = c[mf][nf][3] + by;
                __nv_bfloat162 vh = __floats2bfloat162_rn(v0, v1);
                __nv_bfloat162 wh = __floats2bfloat162_rn(w0, w1);
                __nv_bfloat162 vl = __floats2bfloat162_rn(v0 - __low2float(vh),
                                                          v1 - __high2float(vh));
                __nv_bfloat162 wl = __floats2bfloat162_rn(w0 - __low2float(wh),
                                                          w1 - __high2float(wh));
                const size_t i0 = (size_t)row * nh + col / 2;
                const size_t i1 = (size_t)(row + 8) * nh + col / 2;
                Chu[i0] = bf2u(vh);
                Clu[i0] = bf2u(vl);
                Chu[i1] = bf2u(wh);
                Clu[i1] = bf2u(wl);
                C16u[i0] = h2u(__floats2half2_rn(v0, v1));
                C16u[i1] = h2u(__floats2half2_rn(w0, w1));
            }
        }
    }
}

// ---------------------------------------------------------------------------
// Flash attention (causal): QK^T triple-bf16, PV single-fp16.
// 2-stage cp.async KV ring; stage = KH | KL | V16 (3 planes, 64 x 136 halves).
// Output: fp16 plane.  (round-14 measured-best attention, unchanged)
// ---------------------------------------------------------------------------
#define ATT_C 0.12751666769323707f  // (1/sqrt(128)) * log2(e)
#define RSTR  136
#define KVPLN (64 * RSTR)            // 8704 halves per plane
#define KVSTG (3 * KVPLN)            // 26112 halves per stage
#define ATT_SMEM_BYTES (2 * KVSTG * 2)   // 104448

__global__ __launch_bounds__(256) void flash_attn_tc_kernel(
    const __nv_bfloat16* __restrict__ qkvh, const __nv_bfloat16* __restrict__ qkvl,
    const __half* __restrict__ qkv16,
    __half* __restrict__ att)
{
    extern __shared__ unsigned smu[];
    const unsigned sbase = (unsigned)__cvta_generic_to_shared(smu);

    const int qblk = blockIdx.x;
    const int h    = blockIdx.y;
    const int b    = blockIdx.z;
    const int tid  = threadIdx.x;
    const int lane = tid & 31;
    const int w    = tid >> 5;
    const int g    = lane >> 2;
    const int q    = lane & 3;

    // ---- Stage Q planes (QH at half 0, QL at half 17408; overlays KV ring)
    {
        const int r  = tid >> 1;
        const int c0 = (tid & 1) * 64;
        const size_t gofs = (size_t)(b * SEQ + qblk * 128 + r) * DM3 + h * DHEAD + c0;
        const uint4* qhp = (const uint4*)(qkvh + gofs);
        const uint4* qlp = (const uint4*)(qkvl + gofs);
        #pragma unroll
        for (int i = 0; i < 8; i++) {
            const int hofs = r * RSTR + c0 + 8 * i;
            *(uint4*)(smu + hofs / 2) = qhp[i];
            *(uint4*)(smu + (17408 + hofs) / 2) = qlp[i];
        }
    }
    __syncthreads();

    unsigned qh[8][4], ql[8][4];
    {
        const int row = 16 * w + (lane & 15);
        const int cb  = 8 * (lane >> 4);
        #pragma unroll
        for (int ds = 0; ds < 8; ds++) {
            unsigned a = sbase + 2 * (row * RSTR + 16 * ds + cb);
            ldsm_x4(qh[ds][0], qh[ds][1], qh[ds][2], qh[ds][3], a);
            ldsm_x4(ql[ds][0], ql[ds][1], ql[ds][2], ql[ds][3], a + 2 * 17408);
        }
    }
    __syncthreads();

    const int ntiles = 2 * qblk + 2;

    const int kv_r0 = tid >> 4;
    const int kv_ch = (tid & 15) * 8;
    auto issue_kv = [&](int kt, int stage) {
        const unsigned sb0 = sbase + 2 * stage * KVSTG;
        #pragma unroll
        for (int p = 0; p < 3; p++) {
            const __nv_bfloat16* plane_base =
                (p == 0 ? qkvh + DMODEL
                        : (p == 1 ? qkvl + DMODEL
                                  : (const __nv_bfloat16*)qkv16 + 2 * DMODEL))
                + h * DHEAD + kv_ch;
            #pragma unroll
            for (int j = 0; j < 4; j++) {
                const int row = kv_r0 + 16 * j;
                cpa16(sb0 + 2 * (p * KVPLN + row * RSTR + kv_ch),
                      plane_base + (size_t)(b * SEQ + kt * 64 + row) * DM3);
            }
        }
        cpa_commit();
    };

    issue_kv(0, 0);
    issue_kv(1, 1);

    float o[16][4];
    #pragma unroll
    for (int nf = 0; nf < 16; nf++)
        #pragma unroll
        for (int i = 0; i < 4; i++) o[nf][i] = 0.f;
    float m0 = -1e30f, m1 = -1e30f, l0 = 0.f, l1 = 0.f;

    const int warp_row_max = qblk * 128 + 16 * w + 15;

    for (int kt = 0; kt < ntiles; kt++) {
        asm volatile("cp.async.wait_group 1;\n" ::: "memory");
        __syncthreads();

        const unsigned stg = sbase + 2 * (kt & 1) * KVSTG;

        if (kt * 64 <= warp_row_max) {
            float s[8][4];
            #pragma unroll
            for (int nf = 0; nf < 8; nf++)
                #pragma unroll
                for (int i = 0; i < 4; i++) s[nf][i] = 0.f;

            {
                const int krow   = (lane & 7) + 8 * (lane >> 4);
                const int kchunk = 8 * ((lane >> 3) & 1);
                #pragma unroll
                for (int ds = 0; ds < 8; ds++) {
                    #pragma unroll
                    for (int nfp = 0; nfp < 4; nfp++) {
                        unsigned a = stg + 2 * ((16 * nfp + krow) * RSTR
                                                + 16 * ds + kchunk);
                        unsigned bh0, bh1, bh2, bh3, bl0, bl1, bl2, bl3;
                        ldsm_x4(bh0, bh1, bh2, bh3, a);
                        ldsm_x4(bl0, bl1, bl2, bl3, a + 2 * KVPLN);
                        float* s0 = s[2 * nfp];
                        float* s1 = s[2 * nfp + 1];
                        mma_bf16(s0[0], s0[1], s0[2], s0[3],
                                 qh[ds][0], qh[ds][1], qh[ds][2], qh[ds][3], bh0, bh1);
                        mma_bf16(s0[0], s0[1], s0[2], s0[3],
                                 ql[ds][0], ql[ds][1], ql[ds][2], ql[ds][3], bh0, bh1);
                        mma_bf16(s0[0], s0[1], s0[2], s0[3],
                                 qh[ds][0], qh[ds][1], qh[ds][2], qh[ds][3], bl0, bl1);
                        mma_bf16(s1[0], s1[1], s1[2], s1[3],
                                 qh[ds][0], qh[ds][1], qh[ds][2], qh[ds][3], bh2, bh3);
                        mma_bf16(s1[0], s1[1], s1[2], s1[3],
                                 ql[ds][0], ql[ds][1], ql[ds][2], ql[ds][3], bh2, bh3);
                        mma_bf16(s1[0], s1[1], s1[2], s1[3],
                                 qh[ds][0], qh[ds][1], qh[ds][2], qh[ds][3], bl2, bl3);
                    }
                }
            }

            if (kt >= 2 * qblk) {
                const int row0 = qblk * 128 + 16 * w + g;
                #pragma unroll
                for (int nf = 0; nf < 8; nf++) {
                    const int col = kt * 64 + 8 * nf + 2 * q;
                    if (col     > row0)     s[nf][0] = -CUDART_INF_F;
                    if (col + 1 > row0)     s[nf][1] = -CUDART_INF_F;
                    if (col     > row0 + 8) s[nf][2] = -CUDART_INF_F;
                    if (col + 1 > row0 + 8) s[nf][3] = -CUDART_INF_F;
                }
            }

            float tm0 = -CUDART_INF_F, tm1 = -CUDART_INF_F;
            #pragma unroll
            for (int nf = 0; nf < 8; nf++) {
                tm0 = fmaxf(tm0, fmaxf(s[nf][0], s[nf][1]));
                tm1 = fmaxf(tm1, fmaxf(s[nf][2], s[nf][3]));
            }
            tm0 = fmaxf(tm0, __shfl_xor_sync(0xffffffffu, tm0, 1));
            tm0 = fmaxf(tm0, __shfl_xor_sync(0xffffffffu, tm0, 2));
            tm1 = fmaxf(tm1, __shfl_xor_sync(0xffffffffu, tm1, 1));
            tm1 = fmaxf(tm1, __shfl_xor_sync(0xffffffffu, tm1, 2));

            const float m0n = fmaxf(m0, tm0);
            const float m1n = fmaxf(m1, tm1);
            const float cr0 = exp2f((m0 - m0n) * ATT_C);
            const float cr1 = exp2f((m1 - m1n) * ATT_C);
            m0 = m0n; m1 = m1n;
            l0 *= cr0; l1 *= cr1;
            #pragma unroll
            for (int nf = 0; nf < 16; nf++) {
                o[nf][0] *= cr0; o[nf][1] *= cr0;
                o[nf][2] *= cr1; o[nf][3] *= cr1;
            }

            unsigned ph[8][2];
            #pragma unroll
            for (int nf = 0; nf < 8; nf++) {
                float p0 = exp2f((s[nf][0] - m0) * ATT_C);
                float p1 = exp2f((s[nf][1] - m0) * ATT_C);
                float p2 = exp2f((s[nf][2] - m1) * ATT_C);
                float p3 = exp2f((s[nf][3] - m1) * ATT_C);
                l0 += p0 + p1;
                l1 += p2 + p3;
                ph[nf][0] = h2u(__floats2half2_rn(p0, p1));
                ph[nf][1] = h2u(__floats2half2_rn(p2, p3));
            }

            {
                const int vrow   = (lane & 15);
                const int vchunk = 8 * (lane >> 4);
                #pragma unroll
                for (int j = 0; j < 4; j++) {
                    const unsigned a0 = ph[2 * j][0],     a1 = ph[2 * j][1];
                    const unsigned a2 = ph[2 * j + 1][0], a3 = ph[2 * j + 1][1];
                    #pragma unroll
                    for (int nfp = 0; nfp < 8; nfp++) {
                        unsigned a = stg + 2 * (2 * KVPLN + (16 * j + vrow) * RSTR
                                                + 16 * nfp + vchunk);
                        unsigned v0, v1, v2, v3;
                        ldsm_x4t(v0, v1, v2, v3, a);
                        float* o0 = o[2 * nfp];
                        float* o1 = o[2 * nfp + 1];
                        mma_fp16(o0[0], o0[1], o0[2], o0[3], a0, a1, a2, a3, v0, v1);
                        mma_fp16(o1[0], o1[1], o1[2], o1[3], a0, a1, a2, a3, v2, v3);
                    }
                }
            }
        }

        __syncthreads();
        if (kt + 2 < ntiles) issue_kv(kt + 2, kt & 1);
        else                 cpa_commit();
    }

    l0 += __shfl_xor_sync(0xffffffffu, l0, 1);
    l0 += __shfl_xor_sync(0xffffffffu, l0, 2);
    l1 += __shfl_xor_sync(0xffffffffu, l1, 1);
    l1 += __shfl_xor_sync(0xffffffffu, l1, 2);
    const float inv0 = 1.f / l0;
    const float inv1 = 1.f / l1;

    const size_t row0 = (size_t)(b * SEQ + qblk * 128 + 16 * w + g);
    unsigned* oa = (unsigned*)(att + row0 * DMODEL + h * DHEAD);
    #pragma unroll
    for (int nf = 0; nf < 16; nf++) {
        const int ci = 4 * nf + q;
        oa[ci] = h2u(__floats2half2_rn(o[nf][0] * inv0, o[nf][1] * inv0));
        oa[ci + 4 * DMODEL] = h2u(__floats2half2_rn(o[nf][2] * inv1, o[nf][3] * inv1));
    }
}

// ---------------------------------------------------------------------------
// kernel_launch
// ---------------------------------------------------------------------------
extern "C" void kernel_launch(void* const* d_in, const int* in_sizes, int n_in,
                              void* d_out, int out_size)
{
    const float* x     = (const float*)d_in[0];
    const float* W_qkv = (const float*)d_in[1];
    const float* b_qkv = (const float*)d_in[2];
    const float* W_out = (const float*)d_in[3];
    const float* b_out = (const float*)d_in[4];
    float* out = (float*)d_out;

    __nv_bfloat16 *qh, *ql;
    __half *qv16, *x16, *wq16, *wo16, *att16;
    cudaGetSymbolAddress((void**)&qh,   g_qkvh);
    cudaGetSymbolAddress((void**)&ql,   g_qkvl);
    cudaGetSymbolAddress((void**)&qv16, g_qkv16);
    cudaGetSymbolAddress((void**)&x16,  g_x16);
    cudaGetSymbolAddress((void**)&wq16, g_wqkvt16);
    cudaGetSymbolAddress((void**)&wo16, g_woutt16);
    cudaGetSymbolAddress((void**)&att16, g_att16);

    cudaFuncSetAttribute(flash_attn_tc_kernel,
                         cudaFuncAttributeMaxDynamicSharedMemorySize,
                         ATT_SMEM_BYTES);
    cudaFuncSetAttribute(gemm_fp16_bias_kernel,
                         cudaFuncAttributeMaxDynamicSharedMemorySize,
                         GEMM_SMEM_BYTES);

    // Prep: fp32 -> fp16
    cvt_rm_kernel<<<(MTOT * DMODEL / 4 + 255) / 256, 256>>>(
        (const float4*)x, (uint2*)x16, MTOT * DMODEL / 4);
    cvt_tr_kernel<<<dim3(DM3 / 32, DMODEL / 32), 256>>>(
        W_qkv, wq16, DMODEL, DM3);
    cvt_tr_kernel<<<dim3(DMODEL / 32, DMODEL / 32), 256>>>(
        W_out, wo16, DMODEL, DMODEL);

    // 1) QKV GEMM (fp16) -> bf16 hi/lo planes + fp16 plane
    gemm_fp16_bias_kernel<<<dim3(DM3 / 128, MTOT / 128), 256, GEMM_SMEM_BYTES>>>(
        x16, wq16, b_qkv, nullptr, qh, ql, qv16, MTOT, DM3, DMODEL);

    // 2) Flash attention (QK triple-bf16, PV fp16) -> fp16 plane
    flash_attn_tc_kernel<<<dim3(16, NHEADS, BATCH), 256, ATT_SMEM_BYTES>>>(
        qh, ql, qv16, att16);

    // 3) Output GEMM (fp16) -> fp32
    gemm_fp16_bias_kernel<<<dim3(DMODEL / 128, MTOT / 128), 256, GEMM_SMEM_BYTES>>>(
        att16, wo16, b_out, out, nullptr, nullptr, nullptr, MTOT, DMODEL, DMODEL);
}

// round 16
// speedup vs baseline: 2.7527x; 1.0006x over previous
#include <cuda_runtime.h>
#include <cuda_bf16.h>
#include <cuda_fp16.h>
#include <math_constants.h>

#define BATCH   2
#define SEQ     2048
#define NHEADS  16
#define DHEAD   128
#define DMODEL  2048
#define DM3     6144
#define MTOT    4096

// Scratch (device globals)
__device__ __nv_bfloat16 g_qkvh[(size_t)MTOT * DM3];      // bf16 hi plane (Q,K)
__device__ __nv_bfloat16 g_qkvl[(size_t)MTOT * DM3];      // bf16 lo plane (Q,K)
__device__ __half        g_qkv16[(size_t)MTOT * DM3];     // fp16 plane (V)
__device__ __half        g_x16[(size_t)MTOT * DMODEL];
__device__ __half        g_wqkvt16[(size_t)DM3 * DMODEL]; // fp16 W_qkv^T [N][K]
__device__ __half        g_woutt16[(size_t)DMODEL * DMODEL];
__device__ __half        g_att16[(size_t)MTOT * DMODEL];

// ---------------------------------------------------------------------------
// Helpers
// ---------------------------------------------------------------------------
static __device__ __forceinline__ void mma_bf16(
    float& c0, float& c1, float& c2, float& c3,
    unsigned a0, unsigned a1, unsigned a2, unsigned a3,
    unsigned b0, unsigned b1)
{
    asm volatile(
        "mma.sync.aligned.m16n8k16.row.col.f32.bf16.bf16.f32 "
        "{%0,%1,%2,%3}, {%4,%5,%6,%7}, {%8,%9}, {%0,%1,%2,%3};\n"
        : "+f"(c0), "+f"(c1), "+f"(c2), "+f"(c3)
        : "r"(a0), "r"(a1), "r"(a2), "r"(a3), "r"(b0), "r"(b1));
}
static __device__ __forceinline__ void mma_fp16(
    float& c0, float& c1, float& c2, float& c3,
    unsigned a0, unsigned a1, unsigned a2, unsigned a3,
    unsigned b0, unsigned b1)
{
    asm volatile(
        "mma.sync.aligned.m16n8k16.row.col.f32.f16.f16.f32 "
        "{%0,%1,%2,%3}, {%4,%5,%6,%7}, {%8,%9}, {%0,%1,%2,%3};\n"
        : "+f"(c0), "+f"(c1), "+f"(c2), "+f"(c3)
        : "r"(a0), "r"(a1), "r"(a2), "r"(a3), "r"(b0), "r"(b1));
}
static __device__ __forceinline__ void ldsm_x4(
    unsigned& r0, unsigned& r1, unsigned& r2, unsigned& r3, unsigned addr)
{
    asm volatile("ldmatrix.sync.aligned.m8n8.x4.shared.b16 {%0,%1,%2,%3}, [%4];\n"
                 : "=r"(r0), "=r"(r1), "=r"(r2), "=r"(r3) : "r"(addr));
}
static __device__ __forceinline__ void ldsm_x4t(
    unsigned& r0, unsigned& r1, unsigned& r2, unsigned& r3, unsigned addr)
{
    asm volatile("ldmatrix.sync.aligned.m8n8.x4.trans.shared.b16 {%0,%1,%2,%3}, [%4];\n"
                 : "=r"(r0), "=r"(r1), "=r"(r2), "=r"(r3) : "r"(addr));
}
static __device__ __forceinline__ unsigned bf2u(__nv_bfloat162 v) {
    return *reinterpret_cast<unsigned*>(&v);
}
static __device__ __forceinline__ unsigned h2u(__half2 v) {
    return *reinterpret_cast<unsigned*>(&v);
}
static __device__ __forceinline__ void cpa16(unsigned saddr, const void* g) {
    asm volatile("cp.async.cg.shared.global [%0], [%1], 16;\n"
                 :: "r"(saddr), "l"(g));
}
static __device__ __forceinline__ void cpa_commit() {
    asm volatile("cp.async.commit_group;\n" ::: "memory");
}

// ---------------------------------------------------------------------------
// Prep kernels: fp32 -> fp16
// ---------------------------------------------------------------------------
__global__ __launch_bounds__(256) void cvt_rm_kernel(
    const float4* __restrict__ src, uint2* __restrict__ d, int n4)
{
    int i = blockIdx.x * 256 + threadIdx.x;
    if (i < n4) {
        float4 f = src[i];
        uint2 o;
        o.x = h2u(__floats2half2_rn(f.x, f.y));
        o.y = h2u(__floats2half2_rn(f.z, f.w));
        d[i] = o;
    }
}

__global__ __launch_bounds__(256) void cvt_tr_kernel(
    const float* __restrict__ W, __half* __restrict__ wt, int K, int N)
{
    __shared__ float tile[32][33];
    const int n0 = blockIdx.x * 32, k0 = blockIdx.y * 32;
    const int tx = threadIdx.x & 31, ty = threadIdx.x >> 5;
    #pragma unroll
    for (int i = 0; i < 32; i += 8)
        tile[ty + i][tx] = W[(size_t)(k0 + ty + i) * N + (n0 + tx)];
    __syncthreads();
    #pragma unroll
    for (int i = 0; i < 32; i += 8)
        wt[(size_t)(n0 + ty + i) * K + (k0 + tx)] = __float2half_rn(tile[tx][ty + i]);
}

// ---------------------------------------------------------------------------
// fp16 GEMM: C = A[M,K] @ B^T[N,K] + bias, fp32 accumulate.
// Block 128x128, ktile 32, 256 threads = 8 warps as 2m x 4n, warp tile 64x32
// (halves ldmatrix traffic per mma vs 4m x 2n: 6 ldsm.x4 per 16 mma).
// GST=40 halves, 4-stage cp.async ring (wait_group 2, kt&3), 80KB, 2 CTAs/SM.
// Outputs: fp32 Cf, or (bf16 Ch + bf16 Cl + fp16 C16) planes.
// ---------------------------------------------------------------------------
#define GST 40                       // halves per smem row (32 + 8 pad)
#define PLN (128 * GST)              // plane size in halves (5120)
#define STG_H (2 * PLN)              // stage halves (10240) = 20480 B
#define NSTG 4
#define GEMM_SMEM_BYTES (NSTG * STG_H * 2)   // 81920

__global__ __launch_bounds__(256, 2) void gemm_fp16_bias_kernel(
    const __half* __restrict__ A, const __half* __restrict__ B,
    const float* __restrict__ bias,
    float* __restrict__ Cf,
    __nv_bfloat16* __restrict__ Ch, __nv_bfloat16* __restrict__ Cl,
    __half* __restrict__ C16,
    int M, int N, int K)
{
    extern __shared__ __half sm[];
    const unsigned sb = (unsigned)__cvta_generic_to_shared(sm);

    const int t = threadIdx.x, lane = t & 31, wid = t >> 5;
    const int bm = blockIdx.y, bn = blockIdx.x;
    const int warp_m = wid >> 2;        // 0..1
    const int warp_n = wid & 3;         // 0..3

    const int lr = t >> 1;
    const int ls = (t & 1) * 16;
    const __half* Ag = A + (size_t)(bm * 128 + lr) * K + ls;
    const __half* Bg = B + (size_t)(bn * 128 + lr) * K + ls;
    const unsigned sAd = sb + 2 * (lr * GST + ls);

    float c[4][4][4];   // [mf 0..3][nf(n8) 0..3][4]
    #pragma unroll
    for (int mf = 0; mf < 4; mf++)
        #pragma unroll
        for (int nf = 0; nf < 4; nf++)
            #pragma unroll
            for (int i = 0; i < 4; i++) c[mf][nf][i] = 0.f;

    const int nK = K / 32;

    auto issue_stage = [&](int kt) {
        const int go = kt * 32;
        const unsigned d = sAd + 2 * (kt & 3) * STG_H;
        cpa16(d,                 Ag + go);
        cpa16(d + 16,            Ag + go + 8);
        cpa16(d + 2 * PLN,       Bg + go);
        cpa16(d + 2 * PLN + 16,  Bg + go + 8);
        cpa_commit();
    };

    issue_stage(0);
    issue_stage(1);
    issue_stage(2);

    for (int kt = 0; kt < nK; kt++) {
        asm volatile("cp.async.wait_group 2;\n" ::: "memory");
        __syncthreads();

        if (kt + 3 < nK) issue_stage(kt + 3);

        const unsigned base = sb + 2 * (kt & 3) * STG_H;
        #pragma unroll
        for (int s = 0; s < 2; s++) {
            unsigned ah[4][4];
            #pragma unroll
            for (int mf = 0; mf < 4; mf++) {
                const int row = warp_m * 64 + mf * 16 + (lane & 15);
                const unsigned a = base + 2 * (row * GST + 16 * s + 8 * (lane >> 4));
                ldsm_x4(ah[mf][0], ah[mf][1], ah[mf][2], ah[mf][3], a);
            }
            #pragma unroll
            for (int nfp = 0; nfp < 2; nfp++) {
                const int nrow = warp_n * 32 + nfp * 16 + (lane & 7) + 8 * (lane >> 4);
                const unsigned a = base + 2 * (PLN + nrow * GST
                                               + 16 * s + 8 * ((lane >> 3) & 1));
                unsigned b0, b1, b2, b3;
                ldsm_x4(b0, b1, b2, b3, a);
                #pragma unroll
                for (int mf = 0; mf < 4; mf++) {
                    float* c0 = c[mf][2 * nfp];
                    float* c1 = c[mf][2 * nfp + 1];
                    mma_fp16(c0[0], c0[1], c0[2], c0[3],
                             ah[mf][0], ah[mf][1], ah[mf][2], ah[mf][3], b0, b1);
                    mma_fp16(c1[0], c1[1], c1[2], c1[3],
                             ah[mf][0], ah[mf][1], ah[mf][2], ah[mf][3], b2, b3);
                }
            }
        }
    }

    // Epilogue
    const int g = lane >> 2, q = lane & 3;
    const int crow0 = bm * 128 + warp_m * 64 + g;
    const int ccol0 = bn * 128 + warp_n * 32 + 2 * q;
    if (Cf) {
        #pragma unroll
        for (int nf = 0; nf < 4; nf++) {
            const int col = ccol0 + nf * 8;
            const float bx = bias[col];
            const float by = bias[col + 1];
            #pragma unroll
            for (int mf = 0; mf < 4; mf++) {
                const int row = crow0 + mf * 16;
                *(float2*)(Cf + (size_t)row * N + col) =
                    make_float2(c[mf][nf][0] + bx, c[mf][nf][1] + by);
                *(float2*)(Cf + (size_t)(row + 8) * N + col) =
                    make_float2(c[mf][nf][2] + bx, c[mf][nf][3] + by);
            }
        }
    } else {
        unsigned* Chu = (unsigned*)Ch;
        unsigned* Clu = (unsigned*)Cl;
        unsigned* C16u = (unsigned*)C16;
        const int nh = N / 2;
        #pragma unroll
        for (int nf = 0; nf < 4; nf++) {
            const int col = ccol0 + nf * 8;
            const float bx = bias[col];
            const float by = bias[col + 1];
            #pragma unroll
            for (int mf = 0; mf < 4; mf++) {
                const int row = crow0 + mf * 16;
                float v0 = c[mf][nf][0] + bx, v1 = c[mf][nf][1] + by;
                float w0 = c[mf][nf][2] + bx, w1 = c[mf][nf][3] + by;
                __nv_bfloat162 vh = __floats2bfloat162_rn(v0, v1);
                __nv_bfloat162 wh = __floats2bfloat162_rn(w0, w1);
                __nv_bfloat162 vl = __floats2bfloat162_rn(v0 - __low2float(vh),
                                                          v1 - __high2float(vh));
                __nv_bfloat162 wl = __floats2bfloat162_rn(w0 - __low2float(wh),
                                                          w1 - __high2float(wh));
                const size_t i0 = (size_t)row * nh + col / 2;
                const size_t i1 = (size_t)(row + 8) * nh + col / 2;
                Chu[i0] = bf2u(vh);
                Clu[i0] = bf2u(vl);
                Chu[i1] = bf2u(wh);
                Clu[i1] = bf2u(wl);
                C16u[i0] = h2u(__floats2half2_rn(v0, v1));
                C16u[i1] = h2u(__floats2half2_rn(w0, w1));
            }
        }
    }
}

// ---------------------------------------------------------------------------
// Flash attention (causal): QK^T triple-bf16, PV single-fp16.
// 2-stage cp.async KV ring; stage = KH | KL | V16 (3 planes, 64 x 136 halves).
// Output: fp16 plane.  (unchanged from round 15 — bit-exact)
// ---------------------------------------------------------------------------
#define ATT_C 0.12751666769323707f  // (1/sqrt(128)) * log2(e)
#define RSTR  136
#define KVPLN (64 * RSTR)            // 8704 halves per plane
#define KVSTG (3 * KVPLN)            // 26112 halves per stage
#define ATT_SMEM_BYTES (2 * KVSTG * 2)   // 104448

__global__ __launch_bounds__(256) void flash_attn_tc_kernel(
    const __nv_bfloat16* __restrict__ qkvh, const __nv_bfloat16* __restrict__ qkvl,
    const __half* __restrict__ qkv16,
    __half* __restrict__ att)
{
    extern __shared__ unsigned smu[];
    const unsigned sbase = (unsigned)__cvta_generic_to_shared(smu);

    const int qblk = blockIdx.x;
    const int h    = blockIdx.y;
    const int b    = blockIdx.z;
    const int tid  = threadIdx.x;
    const int lane = tid & 31;
    const int w    = tid >> 5;
    const int g    = lane >> 2;
    const int q    = lane & 3;

    {
        const int r  = tid >> 1;
        const int c0 = (tid & 1) * 64;
        const size_t gofs = (size_t)(b * SEQ + qblk * 128 + r) * DM3 + h * DHEAD + c0;
        const uint4* qhp = (const uint4*)(qkvh + gofs);
        const uint4* qlp = (const uint4*)(qkvl + gofs);
        #pragma unroll
        for (int i = 0; i < 8; i++) {
            const int hofs = r * RSTR + c0 + 8 * i;
            *(uint4*)(smu + hofs / 2) = qhp[i];
            *(uint4*)(smu + (17408 + hofs) / 2) = qlp[i];
        }
    }
    __syncthreads();

    unsigned qh[8][4], ql[8][4];
    {
        const int row = 16 * w + (lane & 15);
        const int cb  = 8 * (lane >> 4);
        #pragma unroll
        for (int ds = 0; ds < 8; ds++) {
            unsigned a = sbase + 2 * (row * RSTR + 16 * ds + cb);
            ldsm_x4(qh[ds][0], qh[ds][1], qh[ds][2], qh[ds][3], a);
            ldsm_x4(ql[ds][0], ql[ds][1], ql[ds][2], ql[ds][3], a + 2 * 17408);
        }
    }
    __syncthreads();

    const int ntiles = 2 * qblk + 2;

    const int kv_r0 = tid >> 4;
    const int kv_ch = (tid & 15) * 8;
    auto issue_kv = [&](int kt, int stage) {
        const unsigned sb0 = sbase + 2 * stage * KVSTG;
        #pragma unroll
        for (int p = 0; p < 3; p++) {
            const __nv_bfloat16* plane_base =
                (p == 0 ? qkvh + DMODEL
                        : (p == 1 ? qkvl + DMODEL
                                  : (const __nv_bfloat16*)qkv16 + 2 * DMODEL))
                + h * DHEAD + kv_ch;
            #pragma unroll
            for (int j = 0; j < 4; j++) {
                const int row = kv_r0 + 16 * j;
                cpa16(sb0 + 2 * (p * KVPLN + row * RSTR + kv_ch),
                      plane_base + (size_t)(b * SEQ + kt * 64 + row) * DM3);
            }
        }
        cpa_commit();
    };

    issue_kv(0, 0);
    issue_kv(1, 1);

    float o[16][4];
    #pragma unroll
    for (int nf = 0; nf < 16; nf++)
        #pragma unroll
        for (int i = 0; i < 4; i++) o[nf][i] = 0.f;
    float m0 = -1e30f, m1 = -1e30f, l0 = 0.f, l1 = 0.f;

    const int warp_row_max = qblk * 128 + 16 * w + 15;

    for (int kt = 0; kt < ntiles; kt++) {
        asm volatile("cp.async.wait_group 1;\n" ::: "memory");
        __syncthreads();

        const unsigned stg = sbase + 2 * (kt & 1) * KVSTG;

        if (kt * 64 <= warp_row_max) {
            float s[8][4];
            #pragma unroll
            for (int nf = 0; nf < 8; nf++)
                #pragma unroll
                for (int i = 0; i < 4; i++) s[nf][i] = 0.f;

            {
                const int krow   = (lane & 7) + 8 * (lane >> 4);
                const int kchunk = 8 * ((lane >> 3) & 1);
                #pragma unroll
                for (int ds = 0; ds < 8; ds++) {
                    #pragma unroll
                    for (int nfp = 0; nfp < 4; nfp++) {
                        unsigned a = stg + 2 * ((16 * nfp + krow) * RSTR
                                                + 16 * ds + kchunk);
                        unsigned bh0, bh1, bh2, bh3, bl0, bl1, bl2, bl3;
                        ldsm_x4(bh0, bh1, bh2, bh3, a);
                        ldsm_x4(bl0, bl1, bl2, bl3, a + 2 * KVPLN);
                        float* s0 = s[2 * nfp];
                        float* s1 = s[2 * nfp + 1];
                        mma_bf16(s0[0], s0[1], s0[2], s0[3],
                                 qh[ds][0], qh[ds][1], qh[ds][2], qh[ds][3], bh0, bh1);
                        mma_bf16(s0[0], s0[1], s0[2], s0[3],
                                 ql[ds][0], ql[ds][1], ql[ds][2], ql[ds][3], bh0, bh1);
                        mma_bf16(s0[0], s0[1], s0[2], s0[3],
                                 qh[ds][0], qh[ds][1], qh[ds][2], qh[ds][3], bl0, bl1);
                        mma_bf16(s1[0], s1[1], s1[2], s1[3],
                                 qh[ds][0], qh[ds][1], qh[ds][2], qh[ds][3], bh2, bh3);
                        mma_bf16(s1[0], s1[1], s1[2], s1[3],
                                 ql[ds][0], ql[ds][1], ql[ds][2], ql[ds][3], bh2, bh3);
                        mma_bf16(s1[0], s1[1], s1[2], s1[3],
                                 qh[ds][0], qh[ds][1], qh[ds][2], qh[ds][3], bl2, bl3);
                    }
                }
            }

            if (kt >= 2 * qblk) {
                const int row0 = qblk * 128 + 16 * w + g;
                #pragma unroll
                for (int nf = 0; nf < 8; nf++) {
                    const int col = kt * 64 + 8 * nf + 2 * q;
                    if (col     > row0)     s[nf][0] = -CUDART_INF_F;
                    if (col + 1 > row0)     s[nf][1] = -CUDART_INF_F;
                    if (col     > row0 + 8) s[nf][2] = -CUDART_INF_F;
                    if (col + 1 > row0 + 8) s[nf][3] = -CUDART_INF_F;
                }
            }

            float tm0 = -CUDART_INF_F, tm1 = -CUDART_INF_F;
            #pragma unroll
            for (int nf = 0; nf < 8; nf++) {
                tm0 = fmaxf(tm0, fmaxf(s[nf][0], s[nf][1]));
                tm1 = fmaxf(tm1, fmaxf(s[nf][2], s[nf][3]));
            }
            tm0 = fmaxf(tm0, __shfl_xor_sync(0xffffffffu, tm0, 1));
            tm0 = fmaxf(tm0, __shfl_xor_sync(0xffffffffu, tm0, 2));
            tm1 = fmaxf(tm1, __shfl_xor_sync(0xffffffffu, tm1, 1));
            tm1 = fmaxf(tm1, __shfl_xor_sync(0xffffffffu, tm1, 2));

            const float m0n = fmaxf(m0, tm0);
            const float m1n = fmaxf(m1, tm1);
            const float cr0 = exp2f((m0 - m0n) * ATT_C);
            const float cr1 = exp2f((m1 - m1n) * ATT_C);
            m0 = m0n; m1 = m1n;
            l0 *= cr0; l1 *= cr1;
            #pragma unroll
            for (int nf = 0; nf < 16; nf++) {
                o[nf][0] *= cr0; o[nf][1] *= cr0;
                o[nf][2] *= cr1; o[nf][3] *= cr1;
            }

            unsigned ph[8][2];
            #pragma unroll
            for (int nf = 0; nf < 8; nf++) {
                float p0 = exp2f((s[nf][0] - m0) * ATT_C);
                float p1 = exp2f((s[nf][1] - m0) * ATT_C);
                float p2 = exp2f((s[nf][2] - m1) * ATT_C);
                float p3 = exp2f((s[nf][3] - m1) * ATT_C);
                l0 += p0 + p1;
                l1 += p2 + p3;
                ph[nf][0] = h2u(__floats2half2_rn(p0, p1));
                ph[nf][1] = h2u(__floats2half2_rn(p2, p3));
            }

            {
                const int vrow   = (lane & 15);
                const int vchunk = 8 * (lane >> 4);
                #pragma unroll
                for (int j = 0; j < 4; j++) {
                    const unsigned a0 = ph[2 * j][0],     a1 = ph[2 * j][1];
                    const unsigned a2 = ph[2 * j + 1][0], a3 = ph[2 * j + 1][1];
                    #pragma unroll
                    for (int nfp = 0; nfp < 8; nfp++) {
                        unsigned a = stg + 2 * (2 * KVPLN + (16 * j + vrow) * RSTR
                                                + 16 * nfp + vchunk);
                        unsigned v0, v1, v2, v3;
                        ldsm_x4t(v0, v1, v2, v3, a);
                        float* o0 = o[2 * nfp];
                        float* o1 = o[2 * nfp + 1];
                        mma_fp16(o0[0], o0[1], o0[2], o0[3], a0, a1, a2, a3, v0, v1);
                        mma_fp16(o1[0], o1[1], o1[2], o1[3], a0, a1, a2, a3, v2, v3);
                    }
                }
            }
        }

        __syncthreads();
        if (kt + 2 < ntiles) issue_kv(kt + 2, kt & 1);
        else                 cpa_commit();
    }

    l0 += __shfl_xor_sync(0xffffffffu, l0, 1);
    l0 += __shfl_xor_sync(0xffffffffu, l0, 2);
    l1 += __shfl_xor_sync(0xffffffffu, l1, 1);
    l1 += __shfl_xor_sync(0xffffffffu, l1, 2);
    const float inv0 = 1.f / l0;
    const float inv1 = 1.f / l1;

    const size_t row0 = (size_t)(b * SEQ + qblk * 128 + 16 * w + g);
    unsigned* oa = (unsigned*)(att + row0 * DMODEL + h * DHEAD);
    #pragma unroll
    for (int nf = 0; nf < 16; nf++) {
        const int ci = 4 * nf + q;
        oa[ci] = h2u(__floats2half2_rn(o[nf][0] * inv0, o[nf][1] * inv0));
        oa[ci + 4 * DMODEL] = h2u(__floats2half2_rn(o[nf][2] * inv1, o[nf][3] * inv1));
    }
}

// ---------------------------------------------------------------------------
// kernel_launch
// ---------------------------------------------------------------------------
extern "C" void kernel_launch(void* const* d_in, const int* in_sizes, int n_in,
                              void* d_out, int out_size)
{
    const float* x     = (const float*)d_in[0];
    const float* W_qkv = (const float*)d_in[1];
    const float* b_qkv = (const float*)d_in[2];
    const float* W_out = (const float*)d_in[3];
    const float* b_out = (const float*)d_in[4];
    float* out = (float*)d_out;

    __nv_bfloat16 *qh, *ql;
    __half *qv16, *x16, *wq16, *wo16, *att16;
    cudaGetSymbolAddress((void**)&qh,   g_qkvh);
    cudaGetSymbolAddress((void**)&ql,   g_qkvl);
    cudaGetSymbolAddress((void**)&qv16, g_qkv16);
    cudaGetSymbolAddress((void**)&x16,  g_x16);
    cudaGetSymbolAddress((void**)&wq16, g_wqkvt16);
    cudaGetSymbolAddress((void**)&wo16, g_woutt16);
    cudaGetSymbolAddress((void**)&att16, g_att16);

    cudaFuncSetAttribute(flash_attn_tc_kernel,
                         cudaFuncAttributeMaxDynamicSharedMemorySize,
                         ATT_SMEM_BYTES);
    cudaFuncSetAttribute(gemm_fp16_bias_kernel,
                         cudaFuncAttributeMaxDynamicSharedMemorySize,
                         GEMM_SMEM_BYTES);

    // Prep: fp32 -> fp16
    cvt_rm_kernel<<<(MTOT * DMODEL / 4 + 255) / 256, 256>>>(
        (const float4*)x, (uint2*)x16, MTOT * DMODEL / 4);
    cvt_tr_kernel<<<dim3(DM3 / 32, DMODEL / 32), 256>>>(
        W_qkv, wq16, DMODEL, DM3);
    cvt_tr_kernel<<<dim3(DMODEL / 32, DMODEL / 32), 256>>>(
        W_out, wo16, DMODEL, DMODEL);

    // 1) QKV GEMM (fp16) -> bf16 hi/lo planes + fp16 plane
    gemm_fp16_bias_kernel<<<dim3(DM3 / 128, MTOT / 128), 256, GEMM_SMEM_BYTES>>>(
        x16, wq16, b_qkv, nullptr, qh, ql, qv16, MTOT, DM3, DMODEL);

    // 2) Flash attention (QK triple-bf16, PV fp16) -> fp16 plane
    flash_attn_tc_kernel<<<dim3(16, NHEADS, BATCH), 256, ATT_SMEM_BYTES>>>(
        qh, ql, qv16, att16);

    // 3) Output GEMM (fp16) -> fp32
    gemm_fp16_bias_kernel<<<dim3(DMODEL / 128, MTOT / 128), 256, GEMM_SMEM_BYTES>>>(
        att16, wo16, b_out, out, nullptr, nullptr, nullptr, MTOT, DMODEL, DMODEL);
}